// round 1
// baseline (speedup 1.0000x reference)
#include <cuda_runtime.h>
#include <stdint.h>

// Per-group scratch (static __device__ — no runtime allocation).
#define NGMAX (1 << 21)  // >= n_groups (1,000,000), with headroom
__device__ unsigned g_smax[NGMAX];   // ordered-mapped float bits of per-group max(s)
__device__ float    g_denom[NGMAX];  // per-group sum of exp(s - smax)
__device__ unsigned g_snmax[NGMAX];  // raw float bits of per-group max(sn) (sn > 0)

#define TEMPERATURE 0.6f
#define EPS_NOISE   1e-4f

// Monotone order-preserving float<->uint mapping (handles negatives).
__device__ __forceinline__ unsigned f2o(float f) {
    unsigned u = __float_as_uint(f);
    return (u & 0x80000000u) ? ~u : (u | 0x80000000u);
}
__device__ __forceinline__ float o2f(unsigned u) {
    return (u & 0x80000000u) ? __uint_as_float(u & 0x7fffffffu)
                             : __uint_as_float(~u);
}

__global__ __launch_bounds__(256) void k_init() {
    int i = blockIdx.x * 256 + threadIdx.x;
    if (i < NGMAX) {
        g_smax[i]  = 0x007fffffu;  // f2o(-inf)
        g_denom[i] = 0.0f;
        g_snmax[i] = 0u;
    }
}

// K1: s = (-log(-log(u)) + logit) / T ; store s into scratch; segment max via atomics.
__global__ __launch_bounds__(256) void k_s_smax(
    const float* __restrict__ logits, const float* __restrict__ ug,
    const int* __restrict__ grp, float* __restrict__ s_out, int E)
{
    int t = blockIdx.x * 256 + threadIdx.x;
    int base = t * 4;
    if (base >= E) return;
    float l[4], u[4], s[4];
    int g[4];
    int cnt;
    if (base + 3 < E) {
        float4 L = reinterpret_cast<const float4*>(logits)[t];
        float4 U = reinterpret_cast<const float4*>(ug)[t];
        int4   G = reinterpret_cast<const int4*>(grp)[t];
        l[0]=L.x; l[1]=L.y; l[2]=L.z; l[3]=L.w;
        u[0]=U.x; u[1]=U.y; u[2]=U.z; u[3]=U.w;
        g[0]=G.x; g[1]=G.y; g[2]=G.z; g[3]=G.w;
        cnt = 4;
    } else {
        cnt = E - base;
        for (int j = 0; j < cnt; j++) {
            l[j] = logits[base + j]; u[j] = ug[base + j]; g[j] = grp[base + j];
        }
    }
#pragma unroll
    for (int j = 0; j < 4; j++)
        if (j < cnt) s[j] = (-logf(-logf(u[j])) + l[j]) / TEMPERATURE;

    if (cnt == 4) {
        reinterpret_cast<float4*>(s_out)[t] = make_float4(s[0], s[1], s[2], s[3]);
    } else {
        for (int j = 0; j < cnt; j++) s_out[base + j] = s[j];
    }
    // Run-aggregated atomic max (groups sorted => consecutive elements share groups)
    unsigned m = f2o(s[0]);
    int cg = g[0];
    for (int j = 1; j < cnt; j++) {
        if (g[j] == cg) { unsigned v = f2o(s[j]); m = (v > m) ? v : m; }
        else { atomicMax(&g_smax[cg], m); cg = g[j]; m = f2o(s[j]); }
    }
    atomicMax(&g_smax[cg], m);
}

// K2: e = exp(s - smax[g]) in place over scratch; segment sum via atomics.
__global__ __launch_bounds__(256) void k_exp_sum(
    float* __restrict__ se, const int* __restrict__ grp, int E)
{
    int t = blockIdx.x * 256 + threadIdx.x;
    int base = t * 4;
    if (base >= E) return;
    float s[4], e[4];
    int g[4];
    int cnt;
    if (base + 3 < E) {
        float4 S = reinterpret_cast<const float4*>(se)[t];
        int4   G = reinterpret_cast<const int4*>(grp)[t];
        s[0]=S.x; s[1]=S.y; s[2]=S.z; s[3]=S.w;
        g[0]=G.x; g[1]=G.y; g[2]=G.z; g[3]=G.w;
        cnt = 4;
    } else {
        cnt = E - base;
        for (int j = 0; j < cnt; j++) { s[j] = se[base + j]; g[j] = grp[base + j]; }
    }
#pragma unroll
    for (int j = 0; j < 4; j++)
        if (j < cnt) e[j] = expf(s[j] - o2f(g_smax[g[j]]));

    if (cnt == 4) {
        reinterpret_cast<float4*>(se)[t] = make_float4(e[0], e[1], e[2], e[3]);
    } else {
        for (int j = 0; j < cnt; j++) se[base + j] = e[j];
    }
    float acc = e[0];
    int cg = g[0];
    for (int j = 1; j < cnt; j++) {
        if (g[j] == cg) acc += e[j];
        else { atomicAdd(&g_denom[cg], acc); cg = g[j]; acc = e[j]; }
    }
    atomicAdd(&g_denom[cg], acc);
}

// K3: soft = e/denom[g] -> out_soft; sn = fma(eps, u_eps, soft); segment max of sn bits.
__global__ __launch_bounds__(256) void k_soft_snmax(
    const float* __restrict__ se, const float* __restrict__ ue,
    const int* __restrict__ grp, float* __restrict__ out_soft, int E)
{
    int t = blockIdx.x * 256 + threadIdx.x;
    int base = t * 4;
    if (base >= E) return;
    float e[4], u[4], soft[4];
    unsigned snb[4];
    int g[4];
    int cnt;
    if (base + 3 < E) {
        float4 S = reinterpret_cast<const float4*>(se)[t];
        float4 U = reinterpret_cast<const float4*>(ue)[t];
        int4   G = reinterpret_cast<const int4*>(grp)[t];
        e[0]=S.x; e[1]=S.y; e[2]=S.z; e[3]=S.w;
        u[0]=U.x; u[1]=U.y; u[2]=U.z; u[3]=U.w;
        g[0]=G.x; g[1]=G.y; g[2]=G.z; g[3]=G.w;
        cnt = 4;
    } else {
        cnt = E - base;
        for (int j = 0; j < cnt; j++) {
            e[j] = se[base + j]; u[j] = ue[base + j]; g[j] = grp[base + j];
        }
    }
#pragma unroll
    for (int j = 0; j < 4; j++) {
        if (j < cnt) {
            soft[j] = e[j] / g_denom[g[j]];
            snb[j] = __float_as_uint(__fmaf_rn(EPS_NOISE, u[j], soft[j]));
        }
    }
    bool vec = (cnt == 4) && ((((uintptr_t)out_soft) & 15) == 0);
    if (vec) {
        reinterpret_cast<float4*>(out_soft)[t] =
            make_float4(soft[0], soft[1], soft[2], soft[3]);
    } else {
        for (int j = 0; j < cnt; j++) out_soft[base + j] = soft[j];
    }
    unsigned m = snb[0];
    int cg = g[0];
    for (int j = 1; j < cnt; j++) {
        if (g[j] == cg) { m = (snb[j] > m) ? snb[j] : m; }
        else { atomicMax(&g_snmax[cg], m); cg = g[j]; m = snb[j]; }
    }
    atomicMax(&g_snmax[cg], m);
}

// K4: recompute sn bit-identically; hot = (bits(sn) == snmax[g]); write st and s_hot.
__global__ __launch_bounds__(256) void k_hot(
    const float* __restrict__ out_soft, const float* __restrict__ ue,
    const int* __restrict__ grp, float* __restrict__ out_st,
    float* __restrict__ out_hot, int E)
{
    int t = blockIdx.x * 256 + threadIdx.x;
    int base = t * 4;
    if (base >= E) return;
    float soft[4], u[4], h[4];
    int g[4];
    int cnt;
    bool vecin = ((((uintptr_t)out_soft) & 15) == 0);
    if (base + 3 < E && vecin) {
        float4 S = reinterpret_cast<const float4*>(out_soft)[t];
        float4 U = reinterpret_cast<const float4*>(ue)[t];
        int4   G = reinterpret_cast<const int4*>(grp)[t];
        soft[0]=S.x; soft[1]=S.y; soft[2]=S.z; soft[3]=S.w;
        u[0]=U.x; u[1]=U.y; u[2]=U.z; u[3]=U.w;
        g[0]=G.x; g[1]=G.y; g[2]=G.z; g[3]=G.w;
        cnt = 4;
    } else {
        cnt = (base + 4 <= E) ? 4 : (E - base);
        for (int j = 0; j < cnt; j++) {
            soft[j] = out_soft[base + j]; u[j] = ue[base + j]; g[j] = grp[base + j];
        }
    }
#pragma unroll
    for (int j = 0; j < 4; j++) {
        if (j < cnt) {
            unsigned snb = __float_as_uint(__fmaf_rn(EPS_NOISE, u[j], soft[j]));
            h[j] = (snb == g_snmax[g[j]]) ? 1.0f : 0.0f;
        }
    }
    if (cnt == 4) {
        reinterpret_cast<float4*>(out_st)[t] = make_float4(h[0], h[1], h[2], h[3]);
        if (((((uintptr_t)out_hot) & 15) == 0)) {
            reinterpret_cast<float4*>(out_hot)[t] = make_float4(h[0], h[1], h[2], h[3]);
        } else {
            for (int j = 0; j < 4; j++) out_hot[base + j] = h[j];
        }
    } else {
        for (int j = 0; j < cnt; j++) { out_st[base + j] = h[j]; out_hot[base + j] = h[j]; }
    }
}

extern "C" void kernel_launch(void* const* d_in, const int* in_sizes, int n_in,
                              void* d_out, int out_size)
{
    const float* logits = (const float*)d_in[0];
    const int*   groups = (const int*)d_in[1];
    const float* u_gum;
    const float* u_eps;
    if (n_in >= 5) {  // logits, logit_groups, n_groups, u_gumbel, u_eps
        u_gum = (const float*)d_in[3];
        u_eps = (const float*)d_in[4];
    } else {          // n_groups not passed as a buffer
        u_gum = (const float*)d_in[2];
        u_eps = (const float*)d_in[3];
    }
    int E = in_sizes[0];

    float* out      = (float*)d_out;
    float* out_st   = out;           // also used as scratch for s, then e
    float* out_hot  = out + (size_t)E;
    float* out_soft = out + 2 * (size_t)E;

    int nthreads = (E + 3) / 4;
    int blocks   = (nthreads + 255) / 256;
    int iblocks  = (NGMAX + 255) / 256;

    k_init<<<iblocks, 256>>>();
    k_s_smax<<<blocks, 256>>>(logits, u_gum, groups, out_st, E);
    k_exp_sum<<<blocks, 256>>>(out_st, groups, E);
    k_soft_snmax<<<blocks, 256>>>(out_st, u_eps, groups, out_soft, E);
    k_hot<<<blocks, 256>>>(out_soft, u_eps, groups, out_st, out_hot, E);
}

// round 2
// speedup vs baseline: 1.1094x; 1.1094x over previous
#include <cuda_runtime.h>
#include <stdint.h>

// Per-group scratch (static __device__ — no runtime allocation).
#define NGMAX (1 << 20)  // >= n_groups (1,000,000)
__device__ float              g_denom[NGMAX];  // per-group sum of exp(s)
__device__ unsigned long long g_pack[NGMAX];   // (sn_bits << 32) | element_index

#define INV_T     (1.0f / 0.6f)
#define EPS_NOISE 1e-4f

// e = exp((gumbel + logit)/T) without max-shift: s in [-13.5, 33] -> no overflow.
// Inner log must be accurate (u near 1 -> log(u) near 0; __logf abs-error would blow up).
__device__ __forceinline__ float gumbel_e(float l, float u) {
    float s = (l - logf(-logf(u))) * INV_T;
    return expf(s);
}

__global__ __launch_bounds__(256) void k_init() {
    int i = blockIdx.x * 256 + threadIdx.x;
    if (i < NGMAX) { g_denom[i] = 0.0f; g_pack[i] = 0ull; }
}

// P1: denom[g] = segment_sum(exp(s)). Run-aggregated atomics (groups sorted).
__global__ __launch_bounds__(256) void k_sum(
    const float* __restrict__ logits, const float* __restrict__ ug,
    const int* __restrict__ grp, int E)
{
    int t = blockIdx.x * 256 + threadIdx.x;
    int base = t * 8;
    if (base >= E) return;
    float l[8], u[8];
    int g[8];
    int cnt;
    if (base + 7 < E) {
        float4 L0 = reinterpret_cast<const float4*>(logits + base)[0];
        float4 L1 = reinterpret_cast<const float4*>(logits + base)[1];
        float4 U0 = reinterpret_cast<const float4*>(ug + base)[0];
        float4 U1 = reinterpret_cast<const float4*>(ug + base)[1];
        int4   G0 = reinterpret_cast<const int4*>(grp + base)[0];
        int4   G1 = reinterpret_cast<const int4*>(grp + base)[1];
        l[0]=L0.x; l[1]=L0.y; l[2]=L0.z; l[3]=L0.w;
        l[4]=L1.x; l[5]=L1.y; l[6]=L1.z; l[7]=L1.w;
        u[0]=U0.x; u[1]=U0.y; u[2]=U0.z; u[3]=U0.w;
        u[4]=U1.x; u[5]=U1.y; u[6]=U1.z; u[7]=U1.w;
        g[0]=G0.x; g[1]=G0.y; g[2]=G0.z; g[3]=G0.w;
        g[4]=G1.x; g[5]=G1.y; g[6]=G1.z; g[7]=G1.w;
        cnt = 8;
    } else {
        cnt = E - base;
        for (int j = 0; j < cnt; j++) {
            l[j] = logits[base + j]; u[j] = ug[base + j]; g[j] = grp[base + j];
        }
    }
    float e[8];
#pragma unroll
    for (int j = 0; j < 8; j++)
        if (j < cnt) e[j] = gumbel_e(l[j], u[j]);

    float acc = e[0];
    int cg = g[0];
    for (int j = 1; j < cnt; j++) {
        if (g[j] == cg) acc += e[j];
        else { atomicAdd(&g_denom[cg], acc); cg = g[j]; acc = e[j]; }
    }
    atomicAdd(&g_denom[cg], acc);
}

// P2: soft = exp(s)/denom[g] -> out_soft; sn = fma(eps, u_eps, soft);
//     argmax via packed (sn_bits, idx) atomicMax; zero-fill st and hot regions.
__global__ __launch_bounds__(256) void k_soft_pick(
    const float* __restrict__ logits, const float* __restrict__ ug,
    const float* __restrict__ ue, const int* __restrict__ grp,
    float* __restrict__ out_soft, float* __restrict__ out_st,
    float* __restrict__ out_hot, int E)
{
    int t = blockIdx.x * 256 + threadIdx.x;
    int base = t * 8;
    if (base >= E) return;
    float l[8], u[8], n[8];
    int g[8];
    int cnt;
    if (base + 7 < E) {
        float4 L0 = reinterpret_cast<const float4*>(logits + base)[0];
        float4 L1 = reinterpret_cast<const float4*>(logits + base)[1];
        float4 U0 = reinterpret_cast<const float4*>(ug + base)[0];
        float4 U1 = reinterpret_cast<const float4*>(ug + base)[1];
        float4 N0 = reinterpret_cast<const float4*>(ue + base)[0];
        float4 N1 = reinterpret_cast<const float4*>(ue + base)[1];
        int4   G0 = reinterpret_cast<const int4*>(grp + base)[0];
        int4   G1 = reinterpret_cast<const int4*>(grp + base)[1];
        l[0]=L0.x; l[1]=L0.y; l[2]=L0.z; l[3]=L0.w;
        l[4]=L1.x; l[5]=L1.y; l[6]=L1.z; l[7]=L1.w;
        u[0]=U0.x; u[1]=U0.y; u[2]=U0.z; u[3]=U0.w;
        u[4]=U1.x; u[5]=U1.y; u[6]=U1.z; u[7]=U1.w;
        n[0]=N0.x; n[1]=N0.y; n[2]=N0.z; n[3]=N0.w;
        n[4]=N1.x; n[5]=N1.y; n[6]=N1.z; n[7]=N1.w;
        g[0]=G0.x; g[1]=G0.y; g[2]=G0.z; g[3]=G0.w;
        g[4]=G1.x; g[5]=G1.y; g[6]=G1.z; g[7]=G1.w;
        cnt = 8;
    } else {
        cnt = E - base;
        for (int j = 0; j < cnt; j++) {
            l[j] = logits[base + j]; u[j] = ug[base + j];
            n[j] = ue[base + j];     g[j] = grp[base + j];
        }
    }

    float soft[8];
    unsigned long long pk[8];
    {
        int   cg = g[0];
        float dn = g_denom[cg];   // gather deduped per run
#pragma unroll
        for (int j = 0; j < 8; j++) {
            if (j < cnt) {
                if (g[j] != cg) { cg = g[j]; dn = g_denom[cg]; }
                float e = gumbel_e(l[j], u[j]);
                soft[j] = e / dn;
                unsigned snb = __float_as_uint(__fmaf_rn(EPS_NOISE, n[j], soft[j]));
                pk[j] = (((unsigned long long)snb) << 32) | (unsigned)(base + j);
            }
        }
    }

    if (cnt == 8) {
        reinterpret_cast<float4*>(out_soft + base)[0] =
            make_float4(soft[0], soft[1], soft[2], soft[3]);
        reinterpret_cast<float4*>(out_soft + base)[1] =
            make_float4(soft[4], soft[5], soft[6], soft[7]);
        float4 z = make_float4(0.f, 0.f, 0.f, 0.f);
        reinterpret_cast<float4*>(out_st + base)[0]  = z;
        reinterpret_cast<float4*>(out_st + base)[1]  = z;
        reinterpret_cast<float4*>(out_hot + base)[0] = z;
        reinterpret_cast<float4*>(out_hot + base)[1] = z;
    } else {
        for (int j = 0; j < cnt; j++) {
            out_soft[base + j] = soft[j];
            out_st[base + j]   = 0.0f;
            out_hot[base + j]  = 0.0f;
        }
    }

    unsigned long long m = pk[0];
    int cg = g[0];
    for (int j = 1; j < cnt; j++) {
        if (g[j] == cg) { if (pk[j] > m) m = pk[j]; }
        else { atomicMax(&g_pack[cg], m); cg = g[j]; m = pk[j]; }
    }
    atomicMax(&g_pack[cg], m);
}

// P3: scatter winners. pack==0 only for untouched groups (sn > 0 always).
__global__ __launch_bounds__(256) void k_scatter(
    float* __restrict__ out_st, float* __restrict__ out_hot)
{
    int i = blockIdx.x * 256 + threadIdx.x;
    if (i < NGMAX) {
        unsigned long long p = g_pack[i];
        if (p) {
            unsigned idx = (unsigned)(p & 0xffffffffu);
            out_st[idx]  = 1.0f;
            out_hot[idx] = 1.0f;
        }
    }
}

extern "C" void kernel_launch(void* const* d_in, const int* in_sizes, int n_in,
                              void* d_out, int out_size)
{
    const float* logits = (const float*)d_in[0];
    const int*   groups = (const int*)d_in[1];
    const float* u_gum;
    const float* u_eps;
    if (n_in >= 5) {  // logits, logit_groups, n_groups, u_gumbel, u_eps
        u_gum = (const float*)d_in[3];
        u_eps = (const float*)d_in[4];
    } else {
        u_gum = (const float*)d_in[2];
        u_eps = (const float*)d_in[3];
    }
    int E = in_sizes[0];

    float* out      = (float*)d_out;
    float* out_st   = out;
    float* out_hot  = out + (size_t)E;
    float* out_soft = out + 2 * (size_t)E;

    int nthreads = (E + 7) / 8;
    int blocks   = (nthreads + 255) / 256;
    int gblocks  = (NGMAX + 255) / 256;

    k_init<<<gblocks, 256>>>();
    k_sum<<<blocks, 256>>>(logits, u_gum, groups, E);
    k_soft_pick<<<blocks, 256>>>(logits, u_gum, u_eps, groups,
                                 out_soft, out_st, out_hot, E);
    k_scatter<<<gblocks, 256>>>(out_st, out_hot);
}

// round 3
// speedup vs baseline: 1.6248x; 1.4645x over previous
#include <cuda_runtime.h>
#include <stdint.h>

#define NGMAX    (1 << 20)   // >= n_groups
#define NBLK_MAX 65536
#define BLOCK    256
#define EPT      8
#define TILE     (BLOCK * EPT)   // 2048
#define TABLE    3072            // group-id span per tile (expected ~102)

__device__ float              g_denom[NGMAX];     // boundary groups: sum of exp(s)
__device__ unsigned long long g_pack[NGMAX];      // boundary groups: (sn_bits<<32)|idx
__device__ unsigned           g_flags[NBLK_MAX];  // per-tile: 1=prefix bdry, 2=suffix bdry, 4=fallback

#define INV_T     (1.0f / 0.6f)
#define EPS_NOISE 1e-4f

// exp((logit + gumbel)/T), no max-shift needed: s in [-14, 33] -> no fp32 overflow.
__device__ __forceinline__ float gumbel_e(float l, float u) {
    return expf((l - logf(-logf(u))) * INV_T);
}

__global__ __launch_bounds__(256) void k_init() {
    int i = blockIdx.x * 256 + threadIdx.x;
    if (i < NGMAX) { g_denom[i] = 0.0f; g_pack[i] = 0ull; }
}

__global__ __launch_bounds__(BLOCK) void k_fused(
    const float* __restrict__ logits, const float* __restrict__ ug,
    const float* __restrict__ ue, const int* __restrict__ grp,
    float* __restrict__ out_soft, float* __restrict__ out_st,
    float* __restrict__ out_hot, int E)
{
    __shared__ float              s_sum[TABLE];
    __shared__ unsigned long long s_pack[TABLE];
    __shared__ int sh_g0, sh_glast, sh_gprev, sh_gnext;

    const int b     = blockIdx.x;
    const int base0 = b * TILE;
    const int tid   = threadIdx.x;
    const int tile_n = min(TILE, E - base0);

    if (tid == 0) {
        sh_g0    = grp[base0];
        sh_glast = grp[base0 + tile_n - 1];
        sh_gprev = (base0 > 0) ? grp[base0 - 1] : -1;
        sh_gnext = (base0 + tile_n < E) ? grp[base0 + tile_n] : -1;
    }
    for (int i = tid; i < TABLE; i += BLOCK) { s_sum[i] = 0.0f; s_pack[i] = 0ull; }
    __syncthreads();

    const int g0    = sh_g0;
    const int glast = sh_glast;
    const bool fallback = (glast - g0 >= TABLE);
    bool g0_b = (sh_gprev == g0);
    bool gl_b = (sh_gnext == glast);
    if (g0 == glast) { bool any = g0_b || gl_b; g0_b = any; gl_b = any; }

    const int base = base0 + tid * EPT;
    const int cnt  = max(0, min(EPT, E - base));

    float l[EPT], u[EPT], n[EPT], e[EPT];
    int g[EPT];
    unsigned long long pk[EPT];

    if (cnt == EPT) {
        float4 L0 = reinterpret_cast<const float4*>(logits + base)[0];
        float4 L1 = reinterpret_cast<const float4*>(logits + base)[1];
        float4 U0 = reinterpret_cast<const float4*>(ug + base)[0];
        float4 U1 = reinterpret_cast<const float4*>(ug + base)[1];
        float4 N0 = reinterpret_cast<const float4*>(ue + base)[0];
        float4 N1 = reinterpret_cast<const float4*>(ue + base)[1];
        int4   G0 = reinterpret_cast<const int4*>(grp + base)[0];
        int4   G1 = reinterpret_cast<const int4*>(grp + base)[1];
        l[0]=L0.x;l[1]=L0.y;l[2]=L0.z;l[3]=L0.w;l[4]=L1.x;l[5]=L1.y;l[6]=L1.z;l[7]=L1.w;
        u[0]=U0.x;u[1]=U0.y;u[2]=U0.z;u[3]=U0.w;u[4]=U1.x;u[5]=U1.y;u[6]=U1.z;u[7]=U1.w;
        n[0]=N0.x;n[1]=N0.y;n[2]=N0.z;n[3]=N0.w;n[4]=N1.x;n[5]=N1.y;n[6]=N1.z;n[7]=N1.w;
        g[0]=G0.x;g[1]=G0.y;g[2]=G0.z;g[3]=G0.w;g[4]=G1.x;g[5]=G1.y;g[6]=G1.z;g[7]=G1.w;
    } else {
        for (int j = 0; j < cnt; j++) {
            l[j]=logits[base+j]; u[j]=ug[base+j]; n[j]=ue[base+j]; g[j]=grp[base+j];
        }
    }

#pragma unroll
    for (int j = 0; j < EPT; j++) {
        if (j < cnt) e[j] = gumbel_e(l[j], u[j]);
    }

    // Accumulate segment sum + provisional packed max of e-based sn?  sn needs soft,
    // which needs denom.  Instead pack (sn_bits, idx) AFTER denom known for interior;
    // for the argmax table we can pack by e (monotone in soft within a segment since
    // denom is constant per segment) -> max e <-> max soft, but sn adds eps*u noise
    // AFTER division, so ordering by e is NOT identical to ordering by sn.
    // Therefore: accumulate only sums now; compute sn/argmax after denom is final.
    if (cnt > 0) {
        float acc = e[0]; int cg = g[0];
        for (int j = 1; j < cnt; j++) {
            if (g[j] == cg) acc += e[j];
            else {
                if (!fallback) atomicAdd(&s_sum[cg - g0], acc);
                else           atomicAdd(&g_denom[cg], acc);
                cg = g[j]; acc = e[j];
            }
        }
        if (!fallback) atomicAdd(&s_sum[cg - g0], acc);
        else           atomicAdd(&g_denom[cg], acc);
    }
    __syncthreads();

    // Push boundary partial sums to global.
    if (tid == 0 && !fallback) {
        if (g0_b)                 atomicAdd(&g_denom[g0],    s_sum[0]);
        if (gl_b && glast != g0)  atomicAdd(&g_denom[glast], s_sum[glast - g0]);
        g_flags[b] = (g0_b ? 1u : 0u) | (gl_b ? 2u : 0u);
    }
    if (tid == 0 && fallback) g_flags[b] = 4u;

    if (fallback) {
        // All elements deferred; also push sn-argmax packed by *local* sn using the
        // (still partial) denom is wrong — in fallback push pk based on final soft is
        // impossible here.  Fallback pushes argmax in the fixup pass instead.
        return;
    }

    // Compute soft and sn, interior argmax via smem, boundary argmax via global atomics.
    float soft[EPT];
    bool def[EPT];
    if (cnt > 0) {
        int cg = g[0];
        float dn = s_sum[cg - g0];
#pragma unroll
        for (int j = 0; j < EPT; j++) {
            if (j < cnt) {
                if (g[j] != cg) { cg = g[j]; dn = s_sum[cg - g0]; }
                soft[j] = e[j] / dn;
                unsigned snb = __float_as_uint(__fmaf_rn(EPS_NOISE, n[j], soft[j]));
                pk[j] = (((unsigned long long)snb) << 32) | (unsigned)(base + j);
                def[j] = (g[j] == g0 && g0_b) || (g[j] == glast && gl_b);
            }
        }
        // argmax accumulation (soft for boundary groups uses local-partial denom —
        // WRONG for boundary, so boundary pk must be pushed with globally-final soft.
        // Boundary elements are deferred entirely to fixup, which recomputes sn from
        // the final denom and uses global atomicMax there.  Interior: smem table.
        float dummy; (void)dummy;
        unsigned long long m = 0; int cg2 = -1;
        for (int j = 0; j < cnt; j++) {
            if (def[j]) continue;
            if (g[j] == cg2) { if (pk[j] > m) m = pk[j]; }
            else {
                if (cg2 >= 0) atomicMax(&s_pack[cg2 - g0], m);
                cg2 = g[j]; m = pk[j];
            }
        }
        if (cg2 >= 0) atomicMax(&s_pack[cg2 - g0], m);
    }
    __syncthreads();

    // Interior writes.
    if (cnt > 0) {
        bool anyDef = false;
        float h[EPT];
#pragma unroll
        for (int j = 0; j < EPT; j++) {
            if (j < cnt) {
                if (def[j]) { anyDef = true; }
                else h[j] = (pk[j] == s_pack[g[j] - g0]) ? 1.0f : 0.0f;
            }
        }
        if (!anyDef && cnt == EPT) {
            reinterpret_cast<float4*>(out_soft + base)[0] = make_float4(soft[0],soft[1],soft[2],soft[3]);
            reinterpret_cast<float4*>(out_soft + base)[1] = make_float4(soft[4],soft[5],soft[6],soft[7]);
            reinterpret_cast<float4*>(out_st  + base)[0]  = make_float4(h[0],h[1],h[2],h[3]);
            reinterpret_cast<float4*>(out_st  + base)[1]  = make_float4(h[4],h[5],h[6],h[7]);
            reinterpret_cast<float4*>(out_hot + base)[0]  = make_float4(h[0],h[1],h[2],h[3]);
            reinterpret_cast<float4*>(out_hot + base)[1]  = make_float4(h[4],h[5],h[6],h[7]);
        } else {
            for (int j = 0; j < cnt; j++) {
                if (!def[j]) {
                    out_soft[base + j] = soft[j];
                    out_st[base + j]   = h[j];
                    out_hot[base + j]  = h[j];
                }
            }
        }
    }
}

// Pass 2a: boundary elements — compute final soft, push global argmax.
__global__ __launch_bounds__(128) void k_bdry_max(
    const float* __restrict__ logits, const float* __restrict__ ug,
    const float* __restrict__ ue, const int* __restrict__ grp,
    float* __restrict__ out_soft, int E)
{
    const int b = blockIdx.x;
    const int base0 = b * TILE;
    const int tile_n = min(TILE, E - base0);
    const unsigned flags = g_flags[b];
    if (!flags) return;
    const int tid = threadIdx.x;

    if (flags & 4u) {  // fallback: all elements
        for (int i = tid; i < tile_n; i += 128) {
            int idx = base0 + i;
            int gg = grp[idx];
            float e = gumbel_e(logits[idx], ug[idx]);
            float soft = e / g_denom[gg];
            out_soft[idx] = soft;
            unsigned snb = __float_as_uint(__fmaf_rn(EPS_NOISE, ue[idx], soft));
            atomicMax(&g_pack[gg], (((unsigned long long)snb) << 32) | (unsigned)idx);
        }
        return;
    }
    int g0 = grp[base0];
    int glast = grp[base0 + tile_n - 1];
    // prefix run
    if (flags & 1u) {
        int i = 0;
        while (i < tile_n) {
            int idx = i + tid;
            bool in = (idx < tile_n) && (grp[base0 + idx] == g0);
            if (in) {
                int a = base0 + idx;
                float e = gumbel_e(logits[a], ug[a]);
                float soft = e / g_denom[g0];
                out_soft[a] = soft;
                unsigned snb = __float_as_uint(__fmaf_rn(EPS_NOISE, ue[a], soft));
                atomicMax(&g_pack[g0], (((unsigned long long)snb) << 32) | (unsigned)a);
            }
            int cont = __syncthreads_and(in || idx >= tile_n);
            if (!cont) break;
            i += 128;
        }
    }
    // suffix run
    if ((flags & 2u) && glast != g0) {
        int i = 0;
        while (i < tile_n) {
            int idx = tile_n - 1 - (i + tid);
            bool in = (idx >= 0) && (grp[base0 + idx] == glast);
            if (in) {
                int a = base0 + idx;
                float e = gumbel_e(logits[a], ug[a]);
                float soft = e / g_denom[glast];
                out_soft[a] = soft;
                unsigned snb = __float_as_uint(__fmaf_rn(EPS_NOISE, ue[a], soft));
                atomicMax(&g_pack[glast], (((unsigned long long)snb) << 32) | (unsigned)a);
            }
            int cont = __syncthreads_and(in || idx < 0);
            if (!cont) break;
            i += 128;
        }
    }
}

// Pass 2b: boundary elements — write st/hot from finalized g_pack.
__global__ __launch_bounds__(128) void k_bdry_write(
    const float* __restrict__ ue, const int* __restrict__ grp,
    const float* __restrict__ out_soft,
    float* __restrict__ out_st, float* __restrict__ out_hot, int E)
{
    const int b = blockIdx.x;
    const int base0 = b * TILE;
    const int tile_n = min(TILE, E - base0);
    const unsigned flags = g_flags[b];
    if (!flags) return;
    const int tid = threadIdx.x;

    auto emit = [&](int a, int gg) {
        float soft = out_soft[a];
        unsigned snb = __float_as_uint(__fmaf_rn(EPS_NOISE, ue[a], soft));
        unsigned long long pk = (((unsigned long long)snb) << 32) | (unsigned)a;
        float h = (pk == g_pack[gg]) ? 1.0f : 0.0f;
        out_st[a] = h; out_hot[a] = h;
    };

    if (flags & 4u) {
        for (int i = tid; i < tile_n; i += 128) emit(base0 + i, grp[base0 + i]);
        return;
    }
    int g0 = grp[base0];
    int glast = grp[base0 + tile_n - 1];
    if (flags & 1u) {
        int i = 0;
        while (i < tile_n) {
            int idx = i + tid;
            bool in = (idx < tile_n) && (grp[base0 + idx] == g0);
            if (in) emit(base0 + idx, g0);
            int cont = __syncthreads_and(in || idx >= tile_n);
            if (!cont) break;
            i += 128;
        }
    }
    if ((flags & 2u) && glast != g0) {
        int i = 0;
        while (i < tile_n) {
            int idx = tile_n - 1 - (i + tid);
            bool in = (idx >= 0) && (grp[base0 + idx] == glast);
            if (in) emit(base0 + idx, glast);
            int cont = __syncthreads_and(in || idx < 0);
            if (!cont) break;
            i += 128;
        }
    }
}

extern "C" void kernel_launch(void* const* d_in, const int* in_sizes, int n_in,
                              void* d_out, int out_size)
{
    const float* logits = (const float*)d_in[0];
    const int*   groups = (const int*)d_in[1];
    const float* u_gum;
    const float* u_eps;
    if (n_in >= 5) { u_gum = (const float*)d_in[3]; u_eps = (const float*)d_in[4]; }
    else           { u_gum = (const float*)d_in[2]; u_eps = (const float*)d_in[3]; }
    int E = in_sizes[0];

    float* out      = (float*)d_out;
    float* out_st   = out;
    float* out_hot  = out + (size_t)E;
    float* out_soft = out + 2 * (size_t)E;

    int nblocks = (E + TILE - 1) / TILE;
    int gblocks = (NGMAX + 255) / 256;

    k_init<<<gblocks, 256>>>();
    k_fused<<<nblocks, BLOCK>>>(logits, u_gum, u_eps, groups,
                                out_soft, out_st, out_hot, E);
    k_bdry_max<<<nblocks, 128>>>(logits, u_gum, u_eps, groups, out_soft, E);
    k_bdry_write<<<nblocks, 128>>>(u_eps, groups, out_soft, out_st, out_hot, E);
}

// round 4
// speedup vs baseline: 1.6968x; 1.0444x over previous
#include <cuda_runtime.h>
#include <stdint.h>

#define NGMAX    (1 << 20)   // >= n_groups
#define NBLK_MAX 65536
#define BLOCK    256
#define EPT      8
#define TILE     (BLOCK * EPT)   // 2048
#define TABLE    3072            // group-id span per tile (expected ~102)

__device__ float    g_denom[NGMAX];    // boundary groups: sum of exp(s)
__device__ unsigned g_snmax[NGMAX];    // boundary groups: max raw bits of sn (sn > 0)
__device__ unsigned g_nbdry;           // worklist counter
__device__ unsigned g_list[NBLK_MAX];  // (flags << 28) | tile_id

#define INV_T     (1.0f / 0.6f)
#define EPS_NOISE 1e-4f

// exp((logit + gumbel)/T), no max-shift needed: s in [-14, 33] -> no fp32 overflow.
// Inner log must be accurate (u near 1 -> -log(u) near 0; fast-log abs error would
// blow up relatively). Outer log / exp are on well-scaled args -> fast intrinsics OK.
__device__ __forceinline__ float gumbel_e(float l, float u) {
    float y = -logf(u);                      // accurate
    return __expf((l - __logf(y)) * INV_T);  // fast
}

__global__ __launch_bounds__(256) void k_init() {
    int i = blockIdx.x * 256 + threadIdx.x;
    if (i < NGMAX) { g_denom[i] = 0.0f; g_snmax[i] = 0u; }
    if (i == 0) g_nbdry = 0u;
}

__global__ __launch_bounds__(BLOCK) void k_fused(
    const float* __restrict__ logits, const float* __restrict__ ug,
    const float* __restrict__ ue, const int* __restrict__ grp,
    float* __restrict__ out_soft, float* __restrict__ out_st,
    float* __restrict__ out_hot, int E)
{
    __shared__ float    s_sum[TABLE];
    __shared__ unsigned s_max[TABLE];
    __shared__ int sh[4];  // g0, glast, gprev, gnext

    const int b      = blockIdx.x;
    const int base0  = b * TILE;
    const int tid    = threadIdx.x;
    const int tile_n = min(TILE, E - base0);

    if (tid == 0) {
        sh[0] = grp[base0];
        sh[1] = grp[base0 + tile_n - 1];
        sh[2] = (base0 > 0) ? grp[base0 - 1] : -1;
        sh[3] = (base0 + tile_n < E) ? grp[base0 + tile_n] : -1;
    }
    __syncthreads();

    const int g0    = sh[0];
    const int glast = sh[1];
    const int span  = glast - g0;
    const bool fallback = (span >= TABLE);
    bool g0_b = (sh[2] == g0);
    bool gl_b = (sh[3] == glast);
    if (g0 == glast) { bool any = g0_b || gl_b; g0_b = any; gl_b = any; }

    if (!fallback) {
        for (int i = tid; i <= span; i += BLOCK) { s_sum[i] = 0.0f; s_max[i] = 0u; }
    }
    __syncthreads();

    const int base = base0 + tid * EPT;
    const int cnt  = max(0, min(EPT, E - base));

    float l[EPT], u[EPT], n[EPT], e[EPT];
    int g[EPT];

    if (cnt == EPT) {
        float4 L0 = reinterpret_cast<const float4*>(logits + base)[0];
        float4 L1 = reinterpret_cast<const float4*>(logits + base)[1];
        float4 U0 = reinterpret_cast<const float4*>(ug + base)[0];
        float4 U1 = reinterpret_cast<const float4*>(ug + base)[1];
        float4 N0 = reinterpret_cast<const float4*>(ue + base)[0];
        float4 N1 = reinterpret_cast<const float4*>(ue + base)[1];
        int4   G0 = reinterpret_cast<const int4*>(grp + base)[0];
        int4   G1 = reinterpret_cast<const int4*>(grp + base)[1];
        l[0]=L0.x;l[1]=L0.y;l[2]=L0.z;l[3]=L0.w;l[4]=L1.x;l[5]=L1.y;l[6]=L1.z;l[7]=L1.w;
        u[0]=U0.x;u[1]=U0.y;u[2]=U0.z;u[3]=U0.w;u[4]=U1.x;u[5]=U1.y;u[6]=U1.z;u[7]=U1.w;
        n[0]=N0.x;n[1]=N0.y;n[2]=N0.z;n[3]=N0.w;n[4]=N1.x;n[5]=N1.y;n[6]=N1.z;n[7]=N1.w;
        g[0]=G0.x;g[1]=G0.y;g[2]=G0.z;g[3]=G0.w;g[4]=G1.x;g[5]=G1.y;g[6]=G1.z;g[7]=G1.w;
    } else {
        for (int j = 0; j < cnt; j++) {
            l[j]=logits[base+j]; u[j]=ug[base+j]; n[j]=ue[base+j]; g[j]=grp[base+j];
        }
    }

#pragma unroll
    for (int j = 0; j < EPT; j++)
        if (j < cnt) e[j] = gumbel_e(l[j], u[j]);

    // Pass A: segment sums (run-aggregated; groups sorted).
    if (cnt > 0) {
        float acc = e[0]; int cg = g[0];
        for (int j = 1; j < cnt; j++) {
            if (g[j] == cg) acc += e[j];
            else {
                if (!fallback) atomicAdd(&s_sum[cg - g0], acc);
                else           atomicAdd(&g_denom[cg], acc);
                cg = g[j]; acc = e[j];
            }
        }
        if (!fallback) atomicAdd(&s_sum[cg - g0], acc);
        else           atomicAdd(&g_denom[cg], acc);
    }
    __syncthreads();

    // Push boundary partial sums + worklist entry.
    if (tid == 0) {
        unsigned fl;
        if (fallback) fl = 4u;
        else {
            if (g0_b)                atomicAdd(&g_denom[g0],    s_sum[0]);
            if (gl_b && glast != g0) atomicAdd(&g_denom[glast], s_sum[span]);
            fl = (g0_b ? 1u : 0u) | (gl_b ? 2u : 0u);
        }
        if (fl) {
            unsigned p = atomicAdd(&g_nbdry, 1u);
            g_list[p] = (fl << 28) | (unsigned)b;
        }
    }
    if (fallback) return;  // everything deferred to fixup

    // Pass B: soft + sn; interior argmax via smem table.
    float soft[EPT];
    unsigned snb[EPT];
    bool def[EPT];
    if (cnt > 0) {
        int cg = g[0];
        float dn = s_sum[cg - g0];
#pragma unroll
        for (int j = 0; j < EPT; j++) {
            if (j < cnt) {
                if (g[j] != cg) { cg = g[j]; dn = s_sum[cg - g0]; }
                soft[j] = e[j] / dn;
                snb[j] = __float_as_uint(__fmaf_rn(EPS_NOISE, n[j], soft[j]));
                def[j] = (g[j] == g0 && g0_b) || (g[j] == glast && gl_b);
            }
        }
        unsigned m = 0; int cg2 = -1;
        for (int j = 0; j < cnt; j++) {
            if (def[j]) continue;
            if (g[j] == cg2) { if (snb[j] > m) m = snb[j]; }
            else {
                if (cg2 >= 0) atomicMax(&s_max[cg2 - g0], m);
                cg2 = g[j]; m = snb[j];
            }
        }
        if (cg2 >= 0) atomicMax(&s_max[cg2 - g0], m);
    }
    __syncthreads();

    // Interior writes (ties all marked 1, matching reference semantics).
    if (cnt > 0) {
        bool anyDef = false;
        float h[EPT];
#pragma unroll
        for (int j = 0; j < EPT; j++) {
            if (j < cnt) {
                if (def[j]) anyDef = true;
                else h[j] = (snb[j] == s_max[g[j] - g0]) ? 1.0f : 0.0f;
            }
        }
        if (!anyDef && cnt == EPT) {
            reinterpret_cast<float4*>(out_soft + base)[0] = make_float4(soft[0],soft[1],soft[2],soft[3]);
            reinterpret_cast<float4*>(out_soft + base)[1] = make_float4(soft[4],soft[5],soft[6],soft[7]);
            reinterpret_cast<float4*>(out_st  + base)[0]  = make_float4(h[0],h[1],h[2],h[3]);
            reinterpret_cast<float4*>(out_st  + base)[1]  = make_float4(h[4],h[5],h[6],h[7]);
            reinterpret_cast<float4*>(out_hot + base)[0]  = make_float4(h[0],h[1],h[2],h[3]);
            reinterpret_cast<float4*>(out_hot + base)[1]  = make_float4(h[4],h[5],h[6],h[7]);
        } else {
            for (int j = 0; j < cnt; j++) {
                if (!def[j]) {
                    out_soft[base + j] = soft[j];
                    out_st[base + j]   = h[j];
                    out_hot[base + j]  = h[j];
                }
            }
        }
    }
}

// Fixup A: boundary elements — final soft, write out_soft, global sn max.
__global__ __launch_bounds__(128) void k_bdry_max(
    const float* __restrict__ logits, const float* __restrict__ ug,
    const float* __restrict__ ue, const int* __restrict__ grp,
    float* __restrict__ out_soft, int E)
{
    const unsigned count = g_nbdry;
    const int tid = threadIdx.x;
    for (unsigned w = blockIdx.x; w < count; w += gridDim.x) {
        unsigned ent = g_list[w];
        unsigned flags = ent >> 28;
        int b = (int)(ent & 0x0fffffffu);
        int base0 = b * TILE;
        int tile_n = min(TILE, E - base0);

        if (flags & 4u) {
            for (int i = tid; i < tile_n; i += 128) {
                int a = base0 + i;
                int gg = grp[a];
                float soft = gumbel_e(logits[a], ug[a]) / g_denom[gg];
                out_soft[a] = soft;
                unsigned snb = __float_as_uint(__fmaf_rn(EPS_NOISE, ue[a], soft));
                atomicMax(&g_snmax[gg], snb);
            }
            __syncthreads();
            continue;
        }
        int g0 = grp[base0];
        int glast = grp[base0 + tile_n - 1];
        if (flags & 1u) {  // prefix run
            int i = 0;
            while (i < tile_n) {
                int idx = i + tid;
                bool in = (idx < tile_n) && (grp[base0 + idx] == g0);
                if (in) {
                    int a = base0 + idx;
                    float soft = gumbel_e(logits[a], ug[a]) / g_denom[g0];
                    out_soft[a] = soft;
                    unsigned snb = __float_as_uint(__fmaf_rn(EPS_NOISE, ue[a], soft));
                    atomicMax(&g_snmax[g0], snb);
                }
                int cont = __syncthreads_and(in || idx >= tile_n);
                if (!cont) break;
                i += 128;
            }
        }
        if ((flags & 2u) && glast != g0) {  // suffix run
            int i = 0;
            while (i < tile_n) {
                int idx = tile_n - 1 - (i + tid);
                bool in = (idx >= 0) && (grp[base0 + idx] == glast);
                if (in) {
                    int a = base0 + idx;
                    float soft = gumbel_e(logits[a], ug[a]) / g_denom[glast];
                    out_soft[a] = soft;
                    unsigned snb = __float_as_uint(__fmaf_rn(EPS_NOISE, ue[a], soft));
                    atomicMax(&g_snmax[glast], snb);
                }
                int cont = __syncthreads_and(in || idx < 0);
                if (!cont) break;
                i += 128;
            }
        }
        __syncthreads();
    }
}

// Fixup B: boundary elements — compare vs finalized g_snmax, write st/hot.
__global__ __launch_bounds__(128) void k_bdry_write(
    const float* __restrict__ ue, const int* __restrict__ grp,
    const float* __restrict__ out_soft,
    float* __restrict__ out_st, float* __restrict__ out_hot, int E)
{
    const unsigned count = g_nbdry;
    const int tid = threadIdx.x;
    for (unsigned w = blockIdx.x; w < count; w += gridDim.x) {
        unsigned ent = g_list[w];
        unsigned flags = ent >> 28;
        int b = (int)(ent & 0x0fffffffu);
        int base0 = b * TILE;
        int tile_n = min(TILE, E - base0);

        auto emit = [&](int a, int gg) {
            float soft = out_soft[a];
            unsigned snb = __float_as_uint(__fmaf_rn(EPS_NOISE, ue[a], soft));
            float h = (snb == g_snmax[gg]) ? 1.0f : 0.0f;
            out_st[a] = h; out_hot[a] = h;
        };

        if (flags & 4u) {
            for (int i = tid; i < tile_n; i += 128) emit(base0 + i, grp[base0 + i]);
            __syncthreads();
            continue;
        }
        int g0 = grp[base0];
        int glast = grp[base0 + tile_n - 1];
        if (flags & 1u) {
            int i = 0;
            while (i < tile_n) {
                int idx = i + tid;
                bool in = (idx < tile_n) && (grp[base0 + idx] == g0);
                if (in) emit(base0 + idx, g0);
                int cont = __syncthreads_and(in || idx >= tile_n);
                if (!cont) break;
                i += 128;
            }
        }
        if ((flags & 2u) && glast != g0) {
            int i = 0;
            while (i < tile_n) {
                int idx = tile_n - 1 - (i + tid);
                bool in = (idx >= 0) && (grp[base0 + idx] == glast);
                if (in) emit(base0 + idx, glast);
                int cont = __syncthreads_and(in || idx < 0);
                if (!cont) break;
                i += 128;
            }
        }
        __syncthreads();
    }
}

extern "C" void kernel_launch(void* const* d_in, const int* in_sizes, int n_in,
                              void* d_out, int out_size)
{
    const float* logits = (const float*)d_in[0];
    const int*   groups = (const int*)d_in[1];
    const float* u_gum;
    const float* u_eps;
    if (n_in >= 5) { u_gum = (const float*)d_in[3]; u_eps = (const float*)d_in[4]; }
    else           { u_gum = (const float*)d_in[2]; u_eps = (const float*)d_in[3]; }
    int E = in_sizes[0];

    float* out      = (float*)d_out;
    float* out_st   = out;
    float* out_hot  = out + (size_t)E;
    float* out_soft = out + 2 * (size_t)E;

    int nblocks = (E + TILE - 1) / TILE;
    int gblocks = (NGMAX + 255) / 256;

    k_init<<<gblocks, 256>>>();
    k_fused<<<nblocks, BLOCK>>>(logits, u_gum, u_eps, groups,
                                out_soft, out_st, out_hot, E);
    k_bdry_max<<<2048, 128>>>(logits, u_gum, u_eps, groups, out_soft, E);
    k_bdry_write<<<2048, 128>>>(u_eps, groups, out_soft, out_st, out_hot, E);
}

// round 5
// speedup vs baseline: 1.8809x; 1.1085x over previous
#include <cuda_runtime.h>
#include <stdint.h>

#define NGMAX    (1 << 20)       // >= n_groups
#define LISTMAX  (1 << 25)       // deferred-element index list (covers worst case)
#define BLOCK    256
#define EPT      8
#define TILE     (BLOCK * EPT)   // 2048
#define TABLE    3072            // group-id span per tile (expected ~102)

__device__ float    g_denom[NGMAX];    // boundary groups: sum of exp(s)
__device__ unsigned g_snmax[NGMAX];    // boundary groups: max raw bits of sn (sn > 0)
__device__ unsigned g_ndef;            // deferred element count
__device__ int      g_list[LISTMAX];   // deferred element indices

#define INV_T     (1.0f / 0.6f)
#define EPS_NOISE 1e-4f

// exp((logit + gumbel)/T), no max-shift needed: s in [-14, 33] -> no fp32 overflow.
// Inner log must be accurate (u near 1 -> -log(u) near 0; fast-log abs error would
// blow up relatively). Outer log / exp are on well-scaled args -> fast intrinsics OK.
__device__ __forceinline__ float gumbel_e(float l, float u) {
    float y = -logf(u);                      // accurate
    return __expf((l - __logf(y)) * INV_T);  // fast
}

// One thread per tile: zero per-group globals only for the tile's edge groups.
__global__ __launch_bounds__(128) void k_init(const int* __restrict__ grp,
                                              int E, int nblocks)
{
    int b = blockIdx.x * 128 + threadIdx.x;
    if (b == 0) g_ndef = 0u;
    if (b >= nblocks) return;
    int base0 = b * TILE;
    int tile_n = min(TILE, E - base0);
    int g0 = grp[base0];
    int glast = grp[base0 + tile_n - 1];
    g_denom[g0] = 0.0f;    g_snmax[g0] = 0u;
    g_denom[glast] = 0.0f; g_snmax[glast] = 0u;
    if (glast - g0 >= TABLE) {  // fallback tile (pathological): zero full span
        for (int g = g0 + 1; g < glast; g++) { g_denom[g] = 0.0f; g_snmax[g] = 0u; }
    }
}

__global__ __launch_bounds__(BLOCK) void k_fused(
    const float* __restrict__ logits, const float* __restrict__ ug,
    const float* __restrict__ ue, const int* __restrict__ grp,
    float* __restrict__ out_soft, float* __restrict__ out_st,
    float* __restrict__ out_hot, int E)
{
    __shared__ float    s_sum[TABLE];
    __shared__ unsigned s_max[TABLE];
    __shared__ int sh[4];  // g0, glast, gprev, gnext

    const int b      = blockIdx.x;
    const int base0  = b * TILE;
    const int tid    = threadIdx.x;
    const int tile_n = min(TILE, E - base0);

    if (tid == 0) {
        sh[0] = grp[base0];
        sh[1] = grp[base0 + tile_n - 1];
        sh[2] = (base0 > 0) ? grp[base0 - 1] : -1;
        sh[3] = (base0 + tile_n < E) ? grp[base0 + tile_n] : -1;
    }
    __syncthreads();

    const int g0    = sh[0];
    const int glast = sh[1];
    const int span  = glast - g0;
    const bool fallback = (span >= TABLE);
    bool g0_b = (sh[2] == g0);
    bool gl_b = (sh[3] == glast);
    if (g0 == glast) { bool any = g0_b || gl_b; g0_b = any; gl_b = any; }

    if (!fallback) {
        for (int i = tid; i <= span; i += BLOCK) { s_sum[i] = 0.0f; s_max[i] = 0u; }
    }
    __syncthreads();

    const int base = base0 + tid * EPT;
    const int cnt  = max(0, min(EPT, E - base));

    float l[EPT], u[EPT], n[EPT], e[EPT];
    int g[EPT];

    if (cnt == EPT) {
        float4 L0 = reinterpret_cast<const float4*>(logits + base)[0];
        float4 L1 = reinterpret_cast<const float4*>(logits + base)[1];
        float4 U0 = reinterpret_cast<const float4*>(ug + base)[0];
        float4 U1 = reinterpret_cast<const float4*>(ug + base)[1];
        float4 N0 = reinterpret_cast<const float4*>(ue + base)[0];
        float4 N1 = reinterpret_cast<const float4*>(ue + base)[1];
        int4   G0 = reinterpret_cast<const int4*>(grp + base)[0];
        int4   G1 = reinterpret_cast<const int4*>(grp + base)[1];
        l[0]=L0.x;l[1]=L0.y;l[2]=L0.z;l[3]=L0.w;l[4]=L1.x;l[5]=L1.y;l[6]=L1.z;l[7]=L1.w;
        u[0]=U0.x;u[1]=U0.y;u[2]=U0.z;u[3]=U0.w;u[4]=U1.x;u[5]=U1.y;u[6]=U1.z;u[7]=U1.w;
        n[0]=N0.x;n[1]=N0.y;n[2]=N0.z;n[3]=N0.w;n[4]=N1.x;n[5]=N1.y;n[6]=N1.z;n[7]=N1.w;
        g[0]=G0.x;g[1]=G0.y;g[2]=G0.z;g[3]=G0.w;g[4]=G1.x;g[5]=G1.y;g[6]=G1.z;g[7]=G1.w;
    } else {
        for (int j = 0; j < cnt; j++) {
            l[j]=logits[base+j]; u[j]=ug[base+j]; n[j]=ue[base+j]; g[j]=grp[base+j];
        }
    }

    // Deferred (boundary / fallback) elements -> element index list.
    bool def[EPT];
#pragma unroll
    for (int j = 0; j < EPT; j++) {
        def[j] = (j < cnt) &&
                 (fallback || (g[j] == g0 && g0_b) || (g[j] == glast && gl_b));
    }
    {
        int nd = 0; int didx[EPT];
#pragma unroll
        for (int j = 0; j < EPT; j++)
            if (def[j]) didx[nd++] = base + j;
        if (nd) {
            unsigned p = atomicAdd(&g_ndef, (unsigned)nd);
            for (int i = 0; i < nd; i++) g_list[p + i] = didx[i];
        }
    }

#pragma unroll
    for (int j = 0; j < EPT; j++)
        if (j < cnt) e[j] = gumbel_e(l[j], u[j]);

    // Pass A: segment sums (run-aggregated; groups sorted).
    if (cnt > 0) {
        float acc = e[0]; int cg = g[0];
        for (int j = 1; j < cnt; j++) {
            if (g[j] == cg) acc += e[j];
            else {
                if (!fallback) atomicAdd(&s_sum[cg - g0], acc);
                else           atomicAdd(&g_denom[cg], acc);
                cg = g[j]; acc = e[j];
            }
        }
        if (!fallback) atomicAdd(&s_sum[cg - g0], acc);
        else           atomicAdd(&g_denom[cg], acc);
    }
    __syncthreads();

    if (tid == 0 && !fallback) {
        if (g0_b)                atomicAdd(&g_denom[g0],    s_sum[0]);
        if (gl_b && glast != g0) atomicAdd(&g_denom[glast], s_sum[span]);
    }
    if (fallback) return;  // everything deferred to fixup

    // Pass B: soft + sn; interior argmax via smem table.
    float soft[EPT];
    unsigned snb[EPT];
    if (cnt > 0) {
        int cg = g[0];
        float dn = s_sum[cg - g0];
#pragma unroll
        for (int j = 0; j < EPT; j++) {
            if (j < cnt) {
                if (g[j] != cg) { cg = g[j]; dn = s_sum[cg - g0]; }
                soft[j] = e[j] / dn;
                snb[j] = __float_as_uint(__fmaf_rn(EPS_NOISE, n[j], soft[j]));
            }
        }
        unsigned m = 0; int cg2 = -1;
        for (int j = 0; j < cnt; j++) {
            if (def[j]) continue;
            if (g[j] == cg2) { if (snb[j] > m) m = snb[j]; }
            else {
                if (cg2 >= 0) atomicMax(&s_max[cg2 - g0], m);
                cg2 = g[j]; m = snb[j];
            }
        }
        if (cg2 >= 0) atomicMax(&s_max[cg2 - g0], m);
    }
    __syncthreads();

    // Interior writes (ties all marked 1, matching reference semantics).
    if (cnt > 0) {
        bool anyDef = false;
        float h[EPT];
#pragma unroll
        for (int j = 0; j < EPT; j++) {
            if (j < cnt) {
                if (def[j]) anyDef = true;
                else h[j] = (snb[j] == s_max[g[j] - g0]) ? 1.0f : 0.0f;
            }
        }
        if (!anyDef && cnt == EPT) {
            reinterpret_cast<float4*>(out_soft + base)[0] = make_float4(soft[0],soft[1],soft[2],soft[3]);
            reinterpret_cast<float4*>(out_soft + base)[1] = make_float4(soft[4],soft[5],soft[6],soft[7]);
            reinterpret_cast<float4*>(out_st  + base)[0]  = make_float4(h[0],h[1],h[2],h[3]);
            reinterpret_cast<float4*>(out_st  + base)[1]  = make_float4(h[4],h[5],h[6],h[7]);
            reinterpret_cast<float4*>(out_hot + base)[0]  = make_float4(h[0],h[1],h[2],h[3]);
            reinterpret_cast<float4*>(out_hot + base)[1]  = make_float4(h[4],h[5],h[6],h[7]);
        } else {
            for (int j = 0; j < cnt; j++) {
                if (!def[j]) {
                    out_soft[base + j] = soft[j];
                    out_st[base + j]   = h[j];
                    out_hot[base + j]  = h[j];
                }
            }
        }
    }
}

// Fixup A: per deferred element — final soft, write out_soft, global sn max.
__global__ __launch_bounds__(256) void k_fix_max(
    const float* __restrict__ logits, const float* __restrict__ ug,
    const float* __restrict__ ue, const int* __restrict__ grp,
    float* __restrict__ out_soft)
{
    unsigned count = g_ndef;
    unsigned stride = gridDim.x * 256;
    for (unsigned i = blockIdx.x * 256 + threadIdx.x; i < count; i += stride) {
        int a = g_list[i];
        int gg = grp[a];
        float soft = gumbel_e(logits[a], ug[a]) / g_denom[gg];
        out_soft[a] = soft;
        unsigned snb = __float_as_uint(__fmaf_rn(EPS_NOISE, ue[a], soft));
        atomicMax(&g_snmax[gg], snb);
    }
}

// Fixup B: per deferred element — compare vs finalized g_snmax, write st/hot.
__global__ __launch_bounds__(256) void k_fix_write(
    const float* __restrict__ ue, const int* __restrict__ grp,
    const float* __restrict__ out_soft,
    float* __restrict__ out_st, float* __restrict__ out_hot)
{
    unsigned count = g_ndef;
    unsigned stride = gridDim.x * 256;
    for (unsigned i = blockIdx.x * 256 + threadIdx.x; i < count; i += stride) {
        int a = g_list[i];
        int gg = grp[a];
        float soft = out_soft[a];
        unsigned snb = __float_as_uint(__fmaf_rn(EPS_NOISE, ue[a], soft));
        float h = (snb == g_snmax[gg]) ? 1.0f : 0.0f;
        out_st[a] = h; out_hot[a] = h;
    }
}

extern "C" void kernel_launch(void* const* d_in, const int* in_sizes, int n_in,
                              void* d_out, int out_size)
{
    const float* logits = (const float*)d_in[0];
    const int*   groups = (const int*)d_in[1];
    const float* u_gum;
    const float* u_eps;
    if (n_in >= 5) { u_gum = (const float*)d_in[3]; u_eps = (const float*)d_in[4]; }
    else           { u_gum = (const float*)d_in[2]; u_eps = (const float*)d_in[3]; }
    int E = in_sizes[0];

    float* out      = (float*)d_out;
    float* out_st   = out;
    float* out_hot  = out + (size_t)E;
    float* out_soft = out + 2 * (size_t)E;

    int nblocks = (E + TILE - 1) / TILE;
    int iblocks = (nblocks + 127) / 128;

    k_init<<<iblocks, 128>>>(groups, E, nblocks);
    k_fused<<<nblocks, BLOCK>>>(logits, u_gum, u_eps, groups,
                                out_soft, out_st, out_hot, E);
    k_fix_max<<<592, 256>>>(logits, u_gum, u_eps, groups, out_soft);
    k_fix_write<<<592, 256>>>(u_eps, groups, out_soft, out_st, out_hot);
}

// round 6
// speedup vs baseline: 1.8867x; 1.0031x over previous
#include <cuda_runtime.h>
#include <stdint.h>

#define NGMAX    (1 << 20)       // >= n_groups
#define LISTMAX  (1 << 25)       // deferred-element index list
#define BGMAX    (1 << 22)       // boundary-group list
#define BLOCK    256
#define EPT      4
#define TILE     (BLOCK * EPT)   // 1024
#define TABLE    1536            // group-id span per tile (expected ~51)

__device__ float              g_denom[NGMAX];    // boundary groups: sum of exp(s)
__device__ unsigned long long g_snpack[NGMAX];   // boundary groups: (sn_bits<<32)|idx
__device__ unsigned g_ndef;                      // deferred element count
__device__ int      g_list[LISTMAX];             // deferred element indices
__device__ unsigned g_nbg;                       // boundary group count
__device__ int      g_bg[BGMAX];                 // boundary group ids (dups ok)

#define INV_T     (1.0f / 0.6f)
#define EPS_NOISE 1e-4f

// exp((logit + gumbel)/T), no max-shift needed: s in [-14, 33] -> no fp32 overflow.
// Inner log must stay accurate (u near 1 -> -log(u) near 0); outer log/exp fast.
__device__ __forceinline__ float gumbel_e(float l, float u) {
    float y = -logf(u);
    return __expf((l - __logf(y)) * INV_T);
}

// One thread per tile: zero per-group globals for edge groups, build boundary list.
__global__ __launch_bounds__(128) void k_init(const int* __restrict__ grp,
                                              int E, int nblocks)
{
    int b = blockIdx.x * 128 + threadIdx.x;
    if (b == 0) { g_ndef = 0u; g_nbg = 0u; }
    if (b >= nblocks) return;
    int base0 = b * TILE;
    int tile_n = min(TILE, E - base0);
    int g0 = grp[base0];
    int glast = grp[base0 + tile_n - 1];
    int gprev = (base0 > 0) ? grp[base0 - 1] : -1;
    int gnext = (base0 + tile_n < E) ? grp[base0 + tile_n] : -1;
    bool g0_b = (gprev == g0);
    bool gl_b = (gnext == glast);
    if (g0 == glast) { bool any = g0_b || gl_b; g0_b = any; gl_b = any; }

    g_denom[g0] = 0.0f;    g_snpack[g0] = 0ull;
    g_denom[glast] = 0.0f; g_snpack[glast] = 0ull;

    if (glast - g0 >= TABLE) {  // pathological fallback tile: whole span boundary
        for (int g = g0 + 1; g < glast; g++) { g_denom[g] = 0.0f; g_snpack[g] = 0ull; }
        unsigned p = atomicAdd(&g_nbg, (unsigned)(glast - g0 + 1));
        for (int g = g0; g <= glast; g++) g_bg[p++] = g;
        return;
    }
    int loc[2]; int nl = 0;
    if (g0_b) loc[nl++] = g0;
    if (gl_b && glast != g0) loc[nl++] = glast;
    if (nl) {
        unsigned p = atomicAdd(&g_nbg, (unsigned)nl);
        for (int i = 0; i < nl; i++) g_bg[p + i] = loc[i];
    }
}

__global__ __launch_bounds__(BLOCK, 6) void k_fused(
    const float* __restrict__ logits, const float* __restrict__ ug,
    const float* __restrict__ ue, const int* __restrict__ grp,
    float* __restrict__ out_soft, float* __restrict__ out_st,
    float* __restrict__ out_hot, int E)
{
    __shared__ float    s_sum[TABLE];
    __shared__ unsigned s_max[TABLE];
    __shared__ int sh[4];  // g0, glast, gprev, gnext

    const int b      = blockIdx.x;
    const int base0  = b * TILE;
    const int tid    = threadIdx.x;
    const int tile_n = min(TILE, E - base0);

    if (tid == 0) {
        sh[0] = grp[base0];
        sh[1] = grp[base0 + tile_n - 1];
        sh[2] = (base0 > 0) ? grp[base0 - 1] : -1;
        sh[3] = (base0 + tile_n < E) ? grp[base0 + tile_n] : -1;
    }
    __syncthreads();

    const int g0    = sh[0];
    const int glast = sh[1];
    const int span  = glast - g0;
    const bool fallback = (span >= TABLE);
    bool g0_b = (sh[2] == g0);
    bool gl_b = (sh[3] == glast);
    if (g0 == glast) { bool any = g0_b || gl_b; g0_b = any; gl_b = any; }

    if (!fallback) {
        for (int i = tid; i <= span; i += BLOCK) { s_sum[i] = 0.0f; s_max[i] = 0u; }
    }
    __syncthreads();

    const int base = base0 + tid * EPT;
    const int cnt  = max(0, min(EPT, E - base));

    float l[EPT], u[EPT], n[EPT], e[EPT];
    int g[EPT];

    if (cnt == EPT) {
        float4 L = *reinterpret_cast<const float4*>(logits + base);
        float4 U = *reinterpret_cast<const float4*>(ug + base);
        float4 N = *reinterpret_cast<const float4*>(ue + base);
        int4   G = *reinterpret_cast<const int4*>(grp + base);
        l[0]=L.x;l[1]=L.y;l[2]=L.z;l[3]=L.w;
        u[0]=U.x;u[1]=U.y;u[2]=U.z;u[3]=U.w;
        n[0]=N.x;n[1]=N.y;n[2]=N.z;n[3]=N.w;
        g[0]=G.x;g[1]=G.y;g[2]=G.z;g[3]=G.w;
    } else {
        for (int j = 0; j < cnt; j++) {
            l[j]=logits[base+j]; u[j]=ug[base+j]; n[j]=ue[base+j]; g[j]=grp[base+j];
        }
    }

    // Deferred (boundary / fallback) elements -> element index list.
    bool def[EPT];
#pragma unroll
    for (int j = 0; j < EPT; j++) {
        def[j] = (j < cnt) &&
                 (fallback || (g[j] == g0 && g0_b) || (g[j] == glast && gl_b));
    }
    {
        int nd = 0; int didx[EPT];
#pragma unroll
        for (int j = 0; j < EPT; j++)
            if (def[j]) didx[nd++] = base + j;
        if (nd) {
            unsigned p = atomicAdd(&g_ndef, (unsigned)nd);
            for (int i = 0; i < nd; i++) g_list[p + i] = didx[i];
        }
    }

#pragma unroll
    for (int j = 0; j < EPT; j++)
        if (j < cnt) e[j] = gumbel_e(l[j], u[j]);

    // Pass A: segment sums (run-aggregated; groups sorted).
    if (cnt > 0) {
        float acc = e[0]; int cg = g[0];
        for (int j = 1; j < cnt; j++) {
            if (g[j] == cg) acc += e[j];
            else {
                if (!fallback) atomicAdd(&s_sum[cg - g0], acc);
                else           atomicAdd(&g_denom[cg], acc);
                cg = g[j]; acc = e[j];
            }
        }
        if (!fallback) atomicAdd(&s_sum[cg - g0], acc);
        else           atomicAdd(&g_denom[cg], acc);
    }
    __syncthreads();

    if (tid == 0 && !fallback) {
        if (g0_b)                atomicAdd(&g_denom[g0],    s_sum[0]);
        if (gl_b && glast != g0) atomicAdd(&g_denom[glast], s_sum[span]);
    }
    if (fallback) return;  // everything deferred to fixup

    // Pass B: soft + sn; interior argmax via smem table.
    float soft[EPT];
    unsigned snb[EPT];
    if (cnt > 0) {
        int cg = g[0];
        float dn = s_sum[cg - g0];
#pragma unroll
        for (int j = 0; j < EPT; j++) {
            if (j < cnt) {
                if (g[j] != cg) { cg = g[j]; dn = s_sum[cg - g0]; }
                soft[j] = e[j] / dn;
                snb[j] = __float_as_uint(__fmaf_rn(EPS_NOISE, n[j], soft[j]));
            }
        }
        unsigned m = 0; int cg2 = -1;
        for (int j = 0; j < cnt; j++) {
            if (def[j]) continue;
            if (g[j] == cg2) { if (snb[j] > m) m = snb[j]; }
            else {
                if (cg2 >= 0) atomicMax(&s_max[cg2 - g0], m);
                cg2 = g[j]; m = snb[j];
            }
        }
        if (cg2 >= 0) atomicMax(&s_max[cg2 - g0], m);
    }
    __syncthreads();

    // Interior writes (ties all marked 1, matching reference semantics).
    if (cnt > 0) {
        bool anyDef = false;
        float h[EPT];
#pragma unroll
        for (int j = 0; j < EPT; j++) {
            if (j < cnt) {
                if (def[j]) anyDef = true;
                else h[j] = (snb[j] == s_max[g[j] - g0]) ? 1.0f : 0.0f;
            }
        }
        if (!anyDef && cnt == EPT) {
            *reinterpret_cast<float4*>(out_soft + base) = make_float4(soft[0],soft[1],soft[2],soft[3]);
            *reinterpret_cast<float4*>(out_st  + base)  = make_float4(h[0],h[1],h[2],h[3]);
            *reinterpret_cast<float4*>(out_hot + base)  = make_float4(h[0],h[1],h[2],h[3]);
        } else {
            for (int j = 0; j < cnt; j++) {
                if (!def[j]) {
                    out_soft[base + j] = soft[j];
                    out_st[base + j]   = h[j];
                    out_hot[base + j]  = h[j];
                }
            }
        }
    }
}

// Fixup A: per deferred element — final soft, zero st/hot, packed global argmax.
__global__ __launch_bounds__(256) void k_fix_max(
    const float* __restrict__ logits, const float* __restrict__ ug,
    const float* __restrict__ ue, const int* __restrict__ grp,
    float* __restrict__ out_soft, float* __restrict__ out_st,
    float* __restrict__ out_hot)
{
    unsigned count = g_ndef;
    unsigned stride = gridDim.x * 256;
    for (unsigned i = blockIdx.x * 256 + threadIdx.x; i < count; i += stride) {
        int a = g_list[i];
        int gg = grp[a];
        float soft = gumbel_e(logits[a], ug[a]) / g_denom[gg];
        out_soft[a] = soft;
        out_st[a]   = 0.0f;
        out_hot[a]  = 0.0f;
        unsigned snb = __float_as_uint(__fmaf_rn(EPS_NOISE, ue[a], soft));
        atomicMax(&g_snpack[gg], (((unsigned long long)snb) << 32) | (unsigned)a);
    }
}

// Fixup B: per boundary group — scatter winner's 1s (dup entries harmless).
__global__ __launch_bounds__(256) void k_scatter(
    float* __restrict__ out_st, float* __restrict__ out_hot)
{
    unsigned count = g_nbg;
    unsigned stride = gridDim.x * 256;
    for (unsigned i = blockIdx.x * 256 + threadIdx.x; i < count; i += stride) {
        int gg = g_bg[i];
        unsigned long long p = g_snpack[gg];
        if (p) {
            unsigned idx = (unsigned)(p & 0xffffffffu);
            out_st[idx]  = 1.0f;
            out_hot[idx] = 1.0f;
        }
    }
}

extern "C" void kernel_launch(void* const* d_in, const int* in_sizes, int n_in,
                              void* d_out, int out_size)
{
    const float* logits = (const float*)d_in[0];
    const int*   groups = (const int*)d_in[1];
    const float* u_gum;
    const float* u_eps;
    if (n_in >= 5) { u_gum = (const float*)d_in[3]; u_eps = (const float*)d_in[4]; }
    else           { u_gum = (const float*)d_in[2]; u_eps = (const float*)d_in[3]; }
    int E = in_sizes[0];

    float* out      = (float*)d_out;
    float* out_st   = out;
    float* out_hot  = out + (size_t)E;
    float* out_soft = out + 2 * (size_t)E;

    int nblocks = (E + TILE - 1) / TILE;
    int iblocks = (nblocks + 127) / 128;

    k_init<<<iblocks, 128>>>(groups, E, nblocks);
    k_fused<<<nblocks, BLOCK>>>(logits, u_gum, u_eps, groups,
                                out_soft, out_st, out_hot, E);
    k_fix_max<<<592, 256>>>(logits, u_gum, u_eps, groups,
                            out_soft, out_st, out_hot);
    k_scatter<<<160, 256>>>(out_st, out_hot);
}

// round 7
// speedup vs baseline: 1.9463x; 1.0316x over previous
#include <cuda_runtime.h>
#include <stdint.h>

#define NGMAX    (1 << 20)       // >= n_groups
#define LISTMAX  (1 << 25)       // deferred-element index list
#define BGMAX    (1 << 22)       // boundary-group list
#define BLOCK    256
#define EPT      8
#define TILE     (BLOCK * EPT)   // 2048
#define TABLE    3072            // group-id span per tile (expected ~102)

__device__ float              g_denom[NGMAX];    // boundary groups: sum of exp(s)
__device__ unsigned long long g_snpack[NGMAX];   // boundary groups: (sn_bits<<32)|idx
__device__ unsigned g_ndef;                      // deferred element count
__device__ int      g_list[LISTMAX];             // deferred element indices
__device__ unsigned g_nbg;                       // boundary group count
__device__ int      g_bg[BGMAX];                 // boundary group ids (dups ok)

#define INV_T     (1.0f / 0.6f)
#define EPS_NOISE 1e-4f

// exp((logit + gumbel)/T), no max-shift needed: s in [-14, 33] -> no fp32 overflow.
// Inner log must stay accurate (u near 1 -> -log(u) near 0); outer log/exp fast.
__device__ __forceinline__ float gumbel_e(float l, float u) {
    float y = -logf(u);
    return __expf((l - __logf(y)) * INV_T);
}

// One thread per tile: zero per-group globals for edge groups, build boundary list.
__global__ __launch_bounds__(128) void k_init(const int* __restrict__ grp,
                                              int E, int nblocks)
{
    int b = blockIdx.x * 128 + threadIdx.x;
    if (b == 0) { g_ndef = 0u; g_nbg = 0u; }
    if (b >= nblocks) return;
    int base0 = b * TILE;
    int tile_n = min(TILE, E - base0);
    int g0 = grp[base0];
    int glast = grp[base0 + tile_n - 1];
    int gprev = (base0 > 0) ? grp[base0 - 1] : -1;
    int gnext = (base0 + tile_n < E) ? grp[base0 + tile_n] : -1;
    bool g0_b = (gprev == g0);
    bool gl_b = (gnext == glast);
    if (g0 == glast) { bool any = g0_b || gl_b; g0_b = any; gl_b = any; }

    g_denom[g0] = 0.0f;    g_snpack[g0] = 0ull;
    g_denom[glast] = 0.0f; g_snpack[glast] = 0ull;

    if (glast - g0 >= TABLE) {  // pathological fallback tile: whole span boundary
        for (int g = g0 + 1; g < glast; g++) { g_denom[g] = 0.0f; g_snpack[g] = 0ull; }
        unsigned p = atomicAdd(&g_nbg, (unsigned)(glast - g0 + 1));
        for (int g = g0; g <= glast; g++) g_bg[p++] = g;
        return;
    }
    int loc[2]; int nl = 0;
    if (g0_b) loc[nl++] = g0;
    if (gl_b && glast != g0) loc[nl++] = glast;
    if (nl) {
        unsigned p = atomicAdd(&g_nbg, (unsigned)nl);
        for (int i = 0; i < nl; i++) g_bg[p + i] = loc[i];
    }
}

__global__ __launch_bounds__(BLOCK) void k_fused(
    const float* __restrict__ logits, const float* __restrict__ ug,
    const float* __restrict__ ue, const int* __restrict__ grp,
    float* __restrict__ out_soft, float* __restrict__ out_st,
    float* __restrict__ out_hot, int E)
{
    __shared__ float    s_sum[TABLE];
    __shared__ unsigned s_max[TABLE];
    __shared__ int sh[4];  // g0, glast, gprev, gnext

    const int b      = blockIdx.x;
    const int base0  = b * TILE;
    const int tid    = threadIdx.x;
    const int tile_n = min(TILE, E - base0);

    if (tid == 0) {
        sh[0] = grp[base0];
        sh[1] = grp[base0 + tile_n - 1];
        sh[2] = (base0 > 0) ? grp[base0 - 1] : -1;
        sh[3] = (base0 + tile_n < E) ? grp[base0 + tile_n] : -1;
    }
    __syncthreads();

    const int g0    = sh[0];
    const int glast = sh[1];
    const int span  = glast - g0;
    const bool fallback = (span >= TABLE);
    bool g0_b = (sh[2] == g0);
    bool gl_b = (sh[3] == glast);
    if (g0 == glast) { bool any = g0_b || gl_b; g0_b = any; gl_b = any; }

    if (!fallback) {
        for (int i = tid; i <= span; i += BLOCK) { s_sum[i] = 0.0f; s_max[i] = 0u; }
    }
    __syncthreads();

    const int base = base0 + tid * EPT;
    const int cnt  = max(0, min(EPT, E - base));

    float l[EPT], u[EPT], n[EPT], e[EPT];
    int g[EPT];

    if (cnt == EPT) {
        float4 L0 = __ldcs(reinterpret_cast<const float4*>(logits + base));
        float4 L1 = __ldcs(reinterpret_cast<const float4*>(logits + base) + 1);
        float4 U0 = __ldcs(reinterpret_cast<const float4*>(ug + base));
        float4 U1 = __ldcs(reinterpret_cast<const float4*>(ug + base) + 1);
        float4 N0 = __ldcs(reinterpret_cast<const float4*>(ue + base));
        float4 N1 = __ldcs(reinterpret_cast<const float4*>(ue + base) + 1);
        int4   G0 = __ldcs(reinterpret_cast<const int4*>(grp + base));
        int4   G1 = __ldcs(reinterpret_cast<const int4*>(grp + base) + 1);
        l[0]=L0.x;l[1]=L0.y;l[2]=L0.z;l[3]=L0.w;l[4]=L1.x;l[5]=L1.y;l[6]=L1.z;l[7]=L1.w;
        u[0]=U0.x;u[1]=U0.y;u[2]=U0.z;u[3]=U0.w;u[4]=U1.x;u[5]=U1.y;u[6]=U1.z;u[7]=U1.w;
        n[0]=N0.x;n[1]=N0.y;n[2]=N0.z;n[3]=N0.w;n[4]=N1.x;n[5]=N1.y;n[6]=N1.z;n[7]=N1.w;
        g[0]=G0.x;g[1]=G0.y;g[2]=G0.z;g[3]=G0.w;g[4]=G1.x;g[5]=G1.y;g[6]=G1.z;g[7]=G1.w;
    } else {
        for (int j = 0; j < cnt; j++) {
            l[j]=logits[base+j]; u[j]=ug[base+j]; n[j]=ue[base+j]; g[j]=grp[base+j];
        }
    }

    // Deferred (boundary / fallback) elements -> element index list.
    bool def[EPT];
#pragma unroll
    for (int j = 0; j < EPT; j++) {
        def[j] = (j < cnt) &&
                 (fallback || (g[j] == g0 && g0_b) || (g[j] == glast && gl_b));
    }
    {
        int nd = 0; int didx[EPT];
#pragma unroll
        for (int j = 0; j < EPT; j++)
            if (def[j]) didx[nd++] = base + j;
        if (nd) {
            unsigned p = atomicAdd(&g_ndef, (unsigned)nd);
            for (int i = 0; i < nd; i++) g_list[p + i] = didx[i];
        }
    }

#pragma unroll
    for (int j = 0; j < EPT; j++)
        if (j < cnt) e[j] = gumbel_e(l[j], u[j]);

    // Pass A: segment sums (run-aggregated; groups sorted).
    if (cnt > 0) {
        float acc = e[0]; int cg = g[0];
        for (int j = 1; j < cnt; j++) {
            if (g[j] == cg) acc += e[j];
            else {
                if (!fallback) atomicAdd(&s_sum[cg - g0], acc);
                else           atomicAdd(&g_denom[cg], acc);
                cg = g[j]; acc = e[j];
            }
        }
        if (!fallback) atomicAdd(&s_sum[cg - g0], acc);
        else           atomicAdd(&g_denom[cg], acc);
    }
    __syncthreads();

    if (tid == 0 && !fallback) {
        if (g0_b)                atomicAdd(&g_denom[g0],    s_sum[0]);
        if (gl_b && glast != g0) atomicAdd(&g_denom[glast], s_sum[span]);
    }
    if (fallback) return;  // everything deferred to fixup

    // Pass B: soft + sn; one reciprocal per run; interior argmax via smem table.
    float soft[EPT];
    unsigned snb[EPT];
    if (cnt > 0) {
        int cg = g[0];
        float rdn = 1.0f / s_sum[cg - g0];
#pragma unroll
        for (int j = 0; j < EPT; j++) {
            if (j < cnt) {
                if (g[j] != cg) { cg = g[j]; rdn = 1.0f / s_sum[cg - g0]; }
                soft[j] = e[j] * rdn;
                snb[j] = __float_as_uint(__fmaf_rn(EPS_NOISE, n[j], soft[j]));
            }
        }
        unsigned m = 0; int cg2 = -1;
        for (int j = 0; j < cnt; j++) {
            if (def[j]) continue;
            if (g[j] == cg2) { if (snb[j] > m) m = snb[j]; }
            else {
                if (cg2 >= 0) atomicMax(&s_max[cg2 - g0], m);
                cg2 = g[j]; m = snb[j];
            }
        }
        if (cg2 >= 0) atomicMax(&s_max[cg2 - g0], m);
    }
    __syncthreads();

    // Interior writes (ties all marked 1, matching reference semantics).
    if (cnt > 0) {
        bool anyDef = false;
        float h[EPT];
#pragma unroll
        for (int j = 0; j < EPT; j++) {
            if (j < cnt) {
                if (def[j]) anyDef = true;
                else h[j] = (snb[j] == s_max[g[j] - g0]) ? 1.0f : 0.0f;
            }
        }
        if (!anyDef && cnt == EPT) {
            __stcs(reinterpret_cast<float4*>(out_soft + base),
                   make_float4(soft[0],soft[1],soft[2],soft[3]));
            __stcs(reinterpret_cast<float4*>(out_soft + base) + 1,
                   make_float4(soft[4],soft[5],soft[6],soft[7]));
            __stcs(reinterpret_cast<float4*>(out_st + base),
                   make_float4(h[0],h[1],h[2],h[3]));
            __stcs(reinterpret_cast<float4*>(out_st + base) + 1,
                   make_float4(h[4],h[5],h[6],h[7]));
            __stcs(reinterpret_cast<float4*>(out_hot + base),
                   make_float4(h[0],h[1],h[2],h[3]));
            __stcs(reinterpret_cast<float4*>(out_hot + base) + 1,
                   make_float4(h[4],h[5],h[6],h[7]));
        } else {
            for (int j = 0; j < cnt; j++) {
                if (!def[j]) {
                    out_soft[base + j] = soft[j];
                    out_st[base + j]   = h[j];
                    out_hot[base + j]  = h[j];
                }
            }
        }
    }
}

// Fixup A: per deferred element — final soft, zero st/hot, packed global argmax.
__global__ __launch_bounds__(256) void k_fix_max(
    const float* __restrict__ logits, const float* __restrict__ ug,
    const float* __restrict__ ue, const int* __restrict__ grp,
    float* __restrict__ out_soft, float* __restrict__ out_st,
    float* __restrict__ out_hot)
{
    unsigned count = g_ndef;
    unsigned stride = gridDim.x * 256;
    for (unsigned i = blockIdx.x * 256 + threadIdx.x; i < count; i += stride) {
        int a = g_list[i];
        int gg = grp[a];
        float soft = gumbel_e(logits[a], ug[a]) / g_denom[gg];
        out_soft[a] = soft;
        out_st[a]   = 0.0f;
        out_hot[a]  = 0.0f;
        unsigned snb = __float_as_uint(__fmaf_rn(EPS_NOISE, ue[a], soft));
        atomicMax(&g_snpack[gg], (((unsigned long long)snb) << 32) | (unsigned)a);
    }
}

// Fixup B: per boundary group — scatter winner's 1s (dup entries harmless).
__global__ __launch_bounds__(256) void k_scatter(
    float* __restrict__ out_st, float* __restrict__ out_hot)
{
    unsigned count = g_nbg;
    unsigned stride = gridDim.x * 256;
    for (unsigned i = blockIdx.x * 256 + threadIdx.x; i < count; i += stride) {
        int gg = g_bg[i];
        unsigned long long p = g_snpack[gg];
        if (p) {
            unsigned idx = (unsigned)(p & 0xffffffffu);
            out_st[idx]  = 1.0f;
            out_hot[idx] = 1.0f;
        }
    }
}

extern "C" void kernel_launch(void* const* d_in, const int* in_sizes, int n_in,
                              void* d_out, int out_size)
{
    const float* logits = (const float*)d_in[0];
    const int*   groups = (const int*)d_in[1];
    const float* u_gum;
    const float* u_eps;
    if (n_in >= 5) { u_gum = (const float*)d_in[3]; u_eps = (const float*)d_in[4]; }
    else           { u_gum = (const float*)d_in[2]; u_eps = (const float*)d_in[3]; }
    int E = in_sizes[0];

    float* out      = (float*)d_out;
    float* out_st   = out;
    float* out_hot  = out + (size_t)E;
    float* out_soft = out + 2 * (size_t)E;

    int nblocks = (E + TILE - 1) / TILE;
    int iblocks = (nblocks + 127) / 128;

    k_init<<<iblocks, 128>>>(groups, E, nblocks);
    k_fused<<<nblocks, BLOCK>>>(logits, u_gum, u_eps, groups,
                                out_soft, out_st, out_hot, E);
    k_fix_max<<<592, 256>>>(logits, u_gum, u_eps, groups,
                            out_soft, out_st, out_hot);
    k_scatter<<<160, 256>>>(out_st, out_hot);
}

// round 9
// speedup vs baseline: 2.2093x; 1.1351x over previous
#include <cuda_runtime.h>
#include <stdint.h>

#define NGMAX    (1 << 20)       // >= n_groups
#define LISTMAX  (1 << 25)       // deferred-element index list
#define NBLK_MAX 65536
#define BGFMAX   (1 << 22)       // fallback boundary-group list
#define BLOCK    256
#define EPT      8
#define TILE     (BLOCK * EPT)   // 2048
#define TABLE    3072            // group-id span per tile (expected ~102)

__device__ float              g_denom[NGMAX];      // boundary groups: sum of exp(s)
__device__ unsigned long long g_snpack[NGMAX];     // boundary groups: (sn_bits<<32)|idx
__device__ unsigned g_ndef;                        // deferred element count (k_fused only)
__device__ int      g_list[LISTMAX];               // deferred element indices
__device__ int      g_bg[2 * NBLK_MAX];            // fixed slots: 2 per tile, -1 = empty
__device__ unsigned g_nbgf;                        // fallback group count (k_fused only)
__device__ int      g_bgf[BGFMAX];                 // fallback group ids

#define INV_T     (1.0f / 0.6f)
#define EPS_NOISE 1e-4f

// exp((logit + gumbel)/T), no max-shift needed: s in [-14, 33] -> no fp32 overflow.
// Inner log must stay accurate (u near 1 -> -log(u) near 0); outer log/exp fast.
__device__ __forceinline__ float gumbel_e(float l, float u) {
    float y = -logf(u);
    return __expf((l - __logf(y)) * INV_T);
}

// One thread per tile. NO data-racing counters: boundary groups go to fixed
// slots g_bg[2b], g_bg[2b+1]; counters reset here are only mutated by k_fused,
// which runs strictly after this kernel completes.
__global__ __launch_bounds__(128) void k_init(const int* __restrict__ grp,
                                              int E, int nblocks)
{
    int b = blockIdx.x * 128 + threadIdx.x;
    if (b == 0) { g_ndef = 0u; g_nbgf = 0u; }
    if (b >= nblocks) return;
    int base0 = b * TILE;
    int tile_n = min(TILE, E - base0);
    int g0 = grp[base0];
    int glast = grp[base0 + tile_n - 1];
    int gprev = (base0 > 0) ? grp[base0 - 1] : -1;
    int gnext = (base0 + tile_n < E) ? grp[base0 + tile_n] : -1;
    bool g0_b = (gprev == g0);
    bool gl_b = (gnext == glast);
    if (g0 == glast) { bool any = g0_b || gl_b; g0_b = any; gl_b = any; }

    g_denom[g0] = 0.0f;    g_snpack[g0] = 0ull;
    g_denom[glast] = 0.0f; g_snpack[glast] = 0ull;

    if (glast - g0 >= TABLE) {  // pathological fallback tile: zero whole span
        for (int g = g0 + 1; g < glast; g++) { g_denom[g] = 0.0f; g_snpack[g] = 0ull; }
        // group list for scatter is pushed by k_fused (after counter reset)
        g_bg[2 * b]     = -1;
        g_bg[2 * b + 1] = -1;
        return;
    }
    g_bg[2 * b]     = g0_b ? g0 : -1;
    g_bg[2 * b + 1] = (gl_b && glast != g0) ? glast : -1;
}

__global__ __launch_bounds__(BLOCK) void k_fused(
    const float* __restrict__ logits, const float* __restrict__ ug,
    const float* __restrict__ ue, const int* __restrict__ grp,
    float* __restrict__ out_soft, float* __restrict__ out_st,
    float* __restrict__ out_hot, int E)
{
    __shared__ float    s_sum[TABLE];
    __shared__ unsigned s_max[TABLE];
    __shared__ int sh[4];  // g0, glast, gprev, gnext

    const int b      = blockIdx.x;
    const int base0  = b * TILE;
    const int tid    = threadIdx.x;
    const int tile_n = min(TILE, E - base0);

    if (tid == 0) {
        sh[0] = grp[base0];
        sh[1] = grp[base0 + tile_n - 1];
        sh[2] = (base0 > 0) ? grp[base0 - 1] : -1;
        sh[3] = (base0 + tile_n < E) ? grp[base0 + tile_n] : -1;
    }
    __syncthreads();

    const int g0    = sh[0];
    const int glast = sh[1];
    const int span  = glast - g0;
    const bool fallback = (span >= TABLE);
    bool g0_b = (sh[2] == g0);
    bool gl_b = (sh[3] == glast);
    if (g0 == glast) { bool any = g0_b || gl_b; g0_b = any; gl_b = any; }

    if (!fallback) {
        for (int i = tid; i <= span; i += BLOCK) { s_sum[i] = 0.0f; s_max[i] = 0u; }
    }
    __syncthreads();

    const int base = base0 + tid * EPT;
    const int cnt  = max(0, min(EPT, E - base));

    float e[EPT];
    int g[EPT];

    // Phase A: load logits/ug/grp only; compute e; l,u die immediately.
    if (cnt == EPT) {
        float4 L0 = __ldcs(reinterpret_cast<const float4*>(logits + base));
        float4 L1 = __ldcs(reinterpret_cast<const float4*>(logits + base) + 1);
        float4 U0 = __ldcs(reinterpret_cast<const float4*>(ug + base));
        float4 U1 = __ldcs(reinterpret_cast<const float4*>(ug + base) + 1);
        int4   G0 = __ldcs(reinterpret_cast<const int4*>(grp + base));
        int4   G1 = __ldcs(reinterpret_cast<const int4*>(grp + base) + 1);
        g[0]=G0.x;g[1]=G0.y;g[2]=G0.z;g[3]=G0.w;g[4]=G1.x;g[5]=G1.y;g[6]=G1.z;g[7]=G1.w;
        e[0]=gumbel_e(L0.x,U0.x); e[1]=gumbel_e(L0.y,U0.y);
        e[2]=gumbel_e(L0.z,U0.z); e[3]=gumbel_e(L0.w,U0.w);
        e[4]=gumbel_e(L1.x,U1.x); e[5]=gumbel_e(L1.y,U1.y);
        e[6]=gumbel_e(L1.z,U1.z); e[7]=gumbel_e(L1.w,U1.w);
    } else {
        for (int j = 0; j < cnt; j++) {
            e[j] = gumbel_e(logits[base+j], ug[base+j]);
            g[j] = grp[base+j];
        }
    }

    // Segment sums (run-aggregated; groups sorted).
    if (cnt > 0) {
        float acc = e[0]; int cg = g[0];
        for (int j = 1; j < cnt; j++) {
            if (g[j] == cg) acc += e[j];
            else {
                if (!fallback) atomicAdd(&s_sum[cg - g0], acc);
                else           atomicAdd(&g_denom[cg], acc);
                cg = g[j]; acc = e[j];
            }
        }
        if (!fallback) atomicAdd(&s_sum[cg - g0], acc);
        else           atomicAdd(&g_denom[cg], acc);
    }

    // Deferred (boundary / fallback) elements -> element index list.
    bool def[EPT];
#pragma unroll
    for (int j = 0; j < EPT; j++) {
        def[j] = (j < cnt) &&
                 (fallback || (g[j] == g0 && g0_b) || (g[j] == glast && gl_b));
    }
    {
        int nd = 0; int didx[EPT];
#pragma unroll
        for (int j = 0; j < EPT; j++)
            if (def[j]) didx[nd++] = base + j;
        if (nd) {
            unsigned p = atomicAdd(&g_ndef, (unsigned)nd);
            for (int i = 0; i < nd; i++) g_list[p + i] = didx[i];
        }
    }

    if (fallback) {
        // Group list for scatter (safe: k_init's counter reset already done).
        if (tid == 0) {
            unsigned p = atomicAdd(&g_nbgf, (unsigned)(span + 1));
            for (int gg = g0; gg <= glast; gg++) g_bgf[p++] = gg;
        }
        // Stash e into out_soft (fixup converts to soft) and zero st/hot.
        if (cnt == EPT) {
            __stcs(reinterpret_cast<float4*>(out_soft + base),
                   make_float4(e[0],e[1],e[2],e[3]));
            __stcs(reinterpret_cast<float4*>(out_soft + base) + 1,
                   make_float4(e[4],e[5],e[6],e[7]));
            float4 z = make_float4(0.f,0.f,0.f,0.f);
            __stcs(reinterpret_cast<float4*>(out_st + base), z);
            __stcs(reinterpret_cast<float4*>(out_st + base) + 1, z);
            __stcs(reinterpret_cast<float4*>(out_hot + base), z);
            __stcs(reinterpret_cast<float4*>(out_hot + base) + 1, z);
        } else {
            for (int j = 0; j < cnt; j++) {
                out_soft[base + j] = e[j];
                out_st[base + j] = 0.f; out_hot[base + j] = 0.f;
            }
        }
        return;
    }
    __syncthreads();

    if (tid == 0) {
        if (g0_b)                atomicAdd(&g_denom[g0],    s_sum[0]);
        if (gl_b && glast != g0) atomicAdd(&g_denom[glast], s_sum[span]);
    }

    // Phase B: load ue now (reads overlap out_soft writes); compute soft,
    // write out_soft immediately (deferred slots stash e); smem argmax.
    unsigned snb[EPT];
    if (cnt > 0) {
        float n[EPT];
        if (cnt == EPT) {
            float4 N0 = __ldcs(reinterpret_cast<const float4*>(ue + base));
            float4 N1 = __ldcs(reinterpret_cast<const float4*>(ue + base) + 1);
            n[0]=N0.x;n[1]=N0.y;n[2]=N0.z;n[3]=N0.w;
            n[4]=N1.x;n[5]=N1.y;n[6]=N1.z;n[7]=N1.w;
        } else {
            for (int j = 0; j < cnt; j++) n[j] = ue[base + j];
        }
        float val[EPT];
        int cg = g[0];
        float rdn = 1.0f / s_sum[cg - g0];
#pragma unroll
        for (int j = 0; j < EPT; j++) {
            if (j < cnt) {
                if (g[j] != cg) { cg = g[j]; rdn = 1.0f / s_sum[cg - g0]; }
                float soft = e[j] * rdn;
                snb[j] = __float_as_uint(__fmaf_rn(EPS_NOISE, n[j], soft));
                val[j] = def[j] ? e[j] : soft;  // deferred slots stash e for fixup
            }
        }
        if (cnt == EPT) {
            __stcs(reinterpret_cast<float4*>(out_soft + base),
                   make_float4(val[0],val[1],val[2],val[3]));
            __stcs(reinterpret_cast<float4*>(out_soft + base) + 1,
                   make_float4(val[4],val[5],val[6],val[7]));
        } else {
            for (int j = 0; j < cnt; j++) out_soft[base + j] = val[j];
        }
        unsigned m = 0; int cg2 = -1;
        for (int j = 0; j < cnt; j++) {
            if (def[j]) continue;
            if (g[j] == cg2) { if (snb[j] > m) m = snb[j]; }
            else {
                if (cg2 >= 0) atomicMax(&s_max[cg2 - g0], m);
                cg2 = g[j]; m = snb[j];
            }
        }
        if (cg2 >= 0) atomicMax(&s_max[cg2 - g0], m);
    }
    __syncthreads();

    // Final phase: h (def slots 0; scatter writes winners), write st/hot.
    if (cnt > 0) {
        float h[EPT];
#pragma unroll
        for (int j = 0; j < EPT; j++) {
            if (j < cnt)
                h[j] = (!def[j] && snb[j] == s_max[g[j] - g0]) ? 1.0f : 0.0f;
        }
        if (cnt == EPT) {
            __stcs(reinterpret_cast<float4*>(out_st + base),
                   make_float4(h[0],h[1],h[2],h[3]));
            __stcs(reinterpret_cast<float4*>(out_st + base) + 1,
                   make_float4(h[4],h[5],h[6],h[7]));
            __stcs(reinterpret_cast<float4*>(out_hot + base),
                   make_float4(h[0],h[1],h[2],h[3]));
            __stcs(reinterpret_cast<float4*>(out_hot + base) + 1,
                   make_float4(h[4],h[5],h[6],h[7]));
        } else {
            for (int j = 0; j < cnt; j++) {
                out_st[base + j]  = h[j];
                out_hot[base + j] = h[j];
            }
        }
    }
}

// Fixup A: per deferred element — e stashed in out_soft; finalize soft + argmax.
__global__ __launch_bounds__(256) void k_fix_max(
    const float* __restrict__ ue, const int* __restrict__ grp,
    float* __restrict__ out_soft)
{
    unsigned count = g_ndef;
    unsigned stride = gridDim.x * 256;
    for (unsigned i = blockIdx.x * 256 + threadIdx.x; i < count; i += stride) {
        int a = g_list[i];
        int gg = grp[a];
        float soft = out_soft[a] / g_denom[gg];
        out_soft[a] = soft;
        unsigned snb = __float_as_uint(__fmaf_rn(EPS_NOISE, ue[a], soft));
        atomicMax(&g_snpack[gg], (((unsigned long long)snb) << 32) | (unsigned)a);
    }
}

// Fixup B: scatter winner's 1s. Fixed slots (2/tile, -1 = empty) + fallback list.
__global__ __launch_bounds__(256) void k_scatter(
    float* __restrict__ out_st, float* __restrict__ out_hot, int nblocks)
{
    unsigned stride = gridDim.x * 256;
    unsigned tid0 = blockIdx.x * 256 + threadIdx.x;
    unsigned nslots = 2u * (unsigned)nblocks;
    for (unsigned i = tid0; i < nslots; i += stride) {
        int gg = g_bg[i];
        if (gg >= 0) {
            unsigned long long p = g_snpack[gg];
            if (p) {
                unsigned idx = (unsigned)(p & 0xffffffffu);
                out_st[idx]  = 1.0f;
                out_hot[idx] = 1.0f;
            }
        }
    }
    unsigned nf = g_nbgf;
    for (unsigned i = tid0; i < nf; i += stride) {
        int gg = g_bgf[i];
        unsigned long long p = g_snpack[gg];
        if (p) {
            unsigned idx = (unsigned)(p & 0xffffffffu);
            out_st[idx]  = 1.0f;
            out_hot[idx] = 1.0f;
        }
    }
}

extern "C" void kernel_launch(void* const* d_in, const int* in_sizes, int n_in,
                              void* d_out, int out_size)
{
    const float* logits = (const float*)d_in[0];
    const int*   groups = (const int*)d_in[1];
    const float* u_gum;
    const float* u_eps;
    if (n_in >= 5) { u_gum = (const float*)d_in[3]; u_eps = (const float*)d_in[4]; }
    else           { u_gum = (const float*)d_in[2]; u_eps = (const float*)d_in[3]; }
    int E = in_sizes[0];

    float* out      = (float*)d_out;
    float* out_st   = out;
    float* out_hot  = out + (size_t)E;
    float* out_soft = out + 2 * (size_t)E;

    int nblocks = (E + TILE - 1) / TILE;
    int iblocks = (nblocks + 127) / 128;

    k_init<<<iblocks, 128>>>(groups, E, nblocks);
    k_fused<<<nblocks, BLOCK>>>(logits, u_gum, u_eps, groups,
                                out_soft, out_st, out_hot, E);
    k_fix_max<<<592, 256>>>(u_eps, groups, out_soft);
    k_scatter<<<592, 256>>>(out_st, out_hot, nblocks);
}